// round 5
// baseline (speedup 1.0000x reference)
#include <cuda_runtime.h>
#include <cuda_fp16.h>
#include <cstdint>

#define B_   64
#define T_   512
#define H_   128
#define E_   300
#define C_   20
#define G4_  512
#define BT_  (B_ * T_)          // 32768

// -------- scratch (static device globals; no runtime allocation) -----------
__device__ __align__(16) float g_xw[2u * BT_ * G4_];   // 128 MB
__device__ __align__(16) float g_h [(unsigned)BT_ * 2 * H_];  // 32 MB
__device__ __align__(16) float g_eexp[(unsigned)BT_ * C_];    // exp(em_j - em_0)
__device__ float g_em0[BT_];
__device__ float g_res[B_];

// ----------------------------- math helpers --------------------------------
__device__ __forceinline__ float fast_sigmoid(float x) {
    return __fdividef(1.0f, 1.0f + __expf(-x));
}
__device__ __forceinline__ float fast_tanh(float x) {
    float ax = fabsf(x);
    float e  = __expf(-2.0f * ax);
    float t  = __fdividef(1.0f - e, 1.0f + e);
    return copysignf(t, x);
}
__device__ __forceinline__ int load_mask(const void* m, long idx, int isbyte) {
    return isbyte ? (int)((const unsigned char*)m)[idx] : ((const int*)m)[idx];
}
__device__ __forceinline__ float2 ffma2(float2 a, float2 b, float2 c) {
    unsigned long long ua = *reinterpret_cast<unsigned long long*>(&a);
    unsigned long long ub = *reinterpret_cast<unsigned long long*>(&b);
    unsigned long long uc = *reinterpret_cast<unsigned long long*>(&c);
    unsigned long long ud;
    asm("fma.rn.f32x2 %0, %1, %2, %3;" : "=l"(ud) : "l"(ua), "l"(ub), "l"(uc));
    return *reinterpret_cast<float2*>(&ud);
}

// ==========================================================================
// Kernel 1: fused embedding gather + input GEMM, register double-buffered.
// ==========================================================================
__global__ void __launch_bounds__(256, 2) k_input_gemm(
    const int*   __restrict__ x,
    const float* __restrict__ emb,
    const float* __restrict__ Wf,  const float* __restrict__ Wb,
    const float* __restrict__ bif, const float* __restrict__ bhf,
    const float* __restrict__ bib, const float* __restrict__ bhb)
{
    __shared__ __align__(16) float sA[16][128];
    __shared__ __align__(16) float sB[16][128];
    __shared__ int sIdx[128];

    const int tid   = threadIdx.x;
    const int m0    = blockIdx.y * 128;
    const int n0    = blockIdx.x * 128;
    const int dir   = n0 >> 9;
    const int gbase = n0 & 511;
    const float* W  = dir ? Wb : Wf;

    if (tid < 128) sIdx[tid] = x[m0 + tid];
    __syncthreads();

    const int row0 = (tid * 2)     >> 2, q0 = (tid * 2)     & 3;
    const int row1 = (tid * 2 + 1) >> 2, q1 = (tid * 2 + 1) & 3;
    const long arow0 = (long)sIdx[row0] * 300, arow1 = (long)sIdx[row1] * 300;
    const long brow0 = (long)(gbase + row0) * 300, brow1 = (long)(gbase + row1) * 300;

    float2 acc[8][4];
#pragma unroll
    for (int i = 0; i < 8; i++)
#pragma unroll
        for (int j = 0; j < 4; j++) acc[i][j] = make_float2(0.f, 0.f);

    const int tm0 = (tid >> 4) << 3;
    const int tn0 = (tid & 15) << 3;

    float4 va0, va1, vb0, vb1;
    {
        int kg0 = 4 * q0, kg1 = 4 * q1;
        va0 = *(const float4*)(emb + arow0 + kg0);
        vb0 = *(const float4*)(W   + brow0 + kg0);
        va1 = *(const float4*)(emb + arow1 + kg1);
        vb1 = *(const float4*)(W   + brow1 + kg1);
    }

    for (int ks = 0; ks < 19; ks++) {
        sA[4*q0+0][row0] = va0.x; sA[4*q0+1][row0] = va0.y;
        sA[4*q0+2][row0] = va0.z; sA[4*q0+3][row0] = va0.w;
        sB[4*q0+0][row0] = vb0.x; sB[4*q0+1][row0] = vb0.y;
        sB[4*q0+2][row0] = vb0.z; sB[4*q0+3][row0] = vb0.w;
        sA[4*q1+0][row1] = va1.x; sA[4*q1+1][row1] = va1.y;
        sA[4*q1+2][row1] = va1.z; sA[4*q1+3][row1] = va1.w;
        sB[4*q1+0][row1] = vb1.x; sB[4*q1+1][row1] = vb1.y;
        sB[4*q1+2][row1] = vb1.z; sB[4*q1+3][row1] = vb1.w;
        __syncthreads();

        if (ks < 18) {
            int k0  = (ks + 1) * 16;
            int kg0 = k0 + 4 * q0, kg1 = k0 + 4 * q1;
            if (kg0 < 300) {
                va0 = *(const float4*)(emb + arow0 + kg0);
                vb0 = *(const float4*)(W   + brow0 + kg0);
            } else { va0 = make_float4(0,0,0,0); vb0 = make_float4(0,0,0,0); }
            if (kg1 < 300) {
                va1 = *(const float4*)(emb + arow1 + kg1);
                vb1 = *(const float4*)(W   + brow1 + kg1);
            } else { va1 = make_float4(0,0,0,0); vb1 = make_float4(0,0,0,0); }
        }

#pragma unroll
        for (int kk = 0; kk < 16; kk++) {
            float a[8];
            float4 b4a = *(const float4*)&sB[kk][tn0];
            float4 b4b = *(const float4*)&sB[kk][tn0 + 4];
            *(float4*)(a)     = *(const float4*)&sA[kk][tm0];
            *(float4*)(a + 4) = *(const float4*)&sA[kk][tm0 + 4];
            float2 b2[4];
            b2[0] = make_float2(b4a.x, b4a.y);
            b2[1] = make_float2(b4a.z, b4a.w);
            b2[2] = make_float2(b4b.x, b4b.y);
            b2[3] = make_float2(b4b.z, b4b.w);
#pragma unroll
            for (int i = 0; i < 8; i++) {
                float2 ai = make_float2(a[i], a[i]);
#pragma unroll
                for (int j = 0; j < 4; j++)
                    acc[i][j] = ffma2(ai, b2[j], acc[i][j]);
            }
        }
        __syncthreads();
    }

    const float* bi = dir ? bib : bif;
    const float* bh = dir ? bhb : bhf;
    float bias[8];
#pragma unroll
    for (int j = 0; j < 8; j++) {
        int g = gbase + tn0 + j;
        bias[j] = bi[g] + bh[g];
    }
    float* outbase = g_xw + (long)dir * BT_ * G4_;
#pragma unroll
    for (int i = 0; i < 8; i++) {
        long rowoff = (long)(m0 + tm0 + i) * G4_ + gbase + tn0;
        float4 o0 = make_float4(acc[i][0].x + bias[0], acc[i][0].y + bias[1],
                                acc[i][1].x + bias[2], acc[i][1].y + bias[3]);
        float4 o1 = make_float4(acc[i][2].x + bias[4], acc[i][2].y + bias[5],
                                acc[i][3].x + bias[6], acc[i][3].y + bias[7]);
        *(float4*)(outbase + rowoff)     = o0;
        *(float4*)(outbase + rowoff + 4) = o1;
    }
}

// ==========================================================================
// Kernel 2: LSTM recurrence — REGISTER-RESIDENT fp16 weights.
//   256 threads, thread owns gates (2t, 2t+1): 128 half2 k-pairs = 64 regs.
//   smem traffic per step is only broadcast h reads (32 LDS.128/warp) and
//   the 512-float gate exchange; the 131KB/step weight crossbar stream from
//   the previous version is gone.
// ==========================================================================
__global__ void __launch_bounds__(256) k_lstm(
    const float* __restrict__ Whf, const float* __restrict__ Whb)
{
    __shared__ __align__(16) float sh[128];
    __shared__ float sg[512];

    const int tid = threadIdx.x;
    const int dir = blockIdx.x >> 6;
    const int b   = blockIdx.x & 63;
    const float* Wh = dir ? Whb : Whf;

    // Weights for gates g0=2*tid, g0+1 as half2 (k even/odd pairs).
    unsigned wA[64], wB[64];
    {
        const float2* r0 = (const float2*)(Wh + (long)(2 * tid)     * 128);
        const float2* r1 = (const float2*)(Wh + (long)(2 * tid + 1) * 128);
#pragma unroll
        for (int p = 0; p < 64; p++) {
            float2 a = r0[p], bb = r1[p];
            __half2 ha = __floats2half2_rn(a.x, a.y);
            __half2 hb = __floats2half2_rn(bb.x, bb.y);
            wA[p] = *(unsigned*)&ha;
            wB[p] = *(unsigned*)&hb;
        }
    }
    if (tid < 128) sh[tid] = 0.0f;
    float c = 0.0f;
    __syncthreads();

    const float* xwp = g_xw + (long)dir * BT_ * G4_ + (long)b * T_ * G4_;
    float* hout = g_h + (long)b * T_ * (2 * H_) + (dir ? H_ : 0);
    const float4* sh4 = (const float4*)sh;

    int t  = dir ? (T_ - 1) : 0;
    const int dt = dir ? -1 : 1;
    const int sec = tid >> 6;   // 0:i 1:f 2:g(tanh) 3:o

    float2 xv_next = *(const float2*)(xwp + (long)t * G4_ + 2 * tid);

    for (int s = 0; s < T_; s++, t += dt) {
        float2 xv = xv_next;
        if (s + 1 < T_)
            xv_next = *(const float2*)(xwp + (long)(t + dt) * G4_ + 2 * tid);

        float2 accA = make_float2(xv.x, 0.0f);
        float2 accB = make_float2(xv.y, 0.0f);
#pragma unroll
        for (int p4 = 0; p4 < 32; p4++) {
            float4 h4 = sh4[p4];                     // broadcast LDS.128
            float2 h01 = make_float2(h4.x, h4.y);
            float2 h23 = make_float2(h4.z, h4.w);
            accA = ffma2(__half22float2(*(__half2*)&wA[2*p4]),     h01, accA);
            accB = ffma2(__half22float2(*(__half2*)&wB[2*p4]),     h01, accB);
            accA = ffma2(__half22float2(*(__half2*)&wA[2*p4 + 1]), h23, accA);
            accB = ffma2(__half22float2(*(__half2*)&wB[2*p4 + 1]), h23, accB);
        }
        float gA = accA.x + accA.y;
        float gB = accB.x + accB.y;
        if (sec == 2) { gA = fast_tanh(gA);    gB = fast_tanh(gB); }
        else          { gA = fast_sigmoid(gA); gB = fast_sigmoid(gB); }
        *(float2*)(sg + 2 * tid) = make_float2(gA, gB);
        __syncthreads();
        if (tid < 128) {
            float cc = fmaf(sg[128 + tid], c, sg[tid] * sg[256 + tid]);
            c = cc;
            float hv = sg[384 + tid] * fast_tanh(cc);
            sh[tid] = hv;
            hout[(long)t * (2 * H_) + tid] = hv;
        }
        __syncthreads();
    }
}

// ==========================================================================
// Kernel 3: logits + CRF emission precompute.
// ==========================================================================
__global__ void __launch_bounds__(256) k_logits(
    const float* __restrict__ fcW, const float* __restrict__ fcb,
    float* __restrict__ logits)
{
    __shared__ float sW[20 * 257];
    __shared__ float shh[16 * 257];
    __shared__ float sl[16 * 20];
    const int tid = threadIdx.x;
    const long bt0 = (long)blockIdx.x * 16;

    for (int i = tid; i < 20 * 256; i += 256) {
        int cc = i >> 8, k = i & 255;
        sW[cc * 257 + k] = fcW[i];
    }
    for (int i = tid; i < 16 * 256; i += 256) {
        int tk = i >> 8, k = i & 255;
        shh[tk * 257 + k] = g_h[(bt0 + tk) * 256 + k];
    }
    __syncthreads();
    for (int o = tid; o < 16 * 20; o += 256) {
        int tk = o / 20, cc = o % 20;
        const float* hr = shh + tk * 257;
        const float* wr = sW  + cc * 257;
        float a0 = 0.f, a1 = 0.f, a2 = 0.f, a3 = 0.f;
#pragma unroll 16
        for (int k = 0; k < 256; k += 4) {
            a0 = fmaf(hr[k + 0], wr[k + 0], a0);
            a1 = fmaf(hr[k + 1], wr[k + 1], a1);
            a2 = fmaf(hr[k + 2], wr[k + 2], a2);
            a3 = fmaf(hr[k + 3], wr[k + 3], a3);
        }
        float lv = fcb[cc] + ((a0 + a1) + (a2 + a3));
        sl[o] = lv;
        logits[(bt0 + tk) * C_ + cc] = lv;
    }
    __syncthreads();
    for (int o = tid; o < 16 * 20; o += 256) {
        int tk = o / 20, cc = o % 20;
        g_eexp[(bt0 + tk) * C_ + cc] = __expf(sl[o] - sl[tk * 20]);
        if (cc == 0) g_em0[bt0 + tk] = sl[tk * 20];
    }
}

// ==========================================================================
// Kernel 4: CRF — exp-space scan from SMEM-resident tables. 128 threads:
//   all preload ee/em0 into smem (bulk float4), then warp 0 runs the scan
//   (LDS-only hot loop, zero MUFU) while warps 1-3 compute log_num.
// ==========================================================================
__global__ void __launch_bounds__(128) k_crf(
    const float* __restrict__ logits,
    const int*   __restrict__ tags,
    const void*  __restrict__ maskp,
    const float* __restrict__ trans)
{
    __shared__ __align__(16) float sEE[T_ * C_];   // 40960 B
    __shared__ __align__(16) float sEM0[T_];       // 2048 B
    __shared__ float sT[400];
    __shared__ float sPart[8];                      // log_num partials + len
    const int tid  = threadIdx.x;
    const int lane = tid & 31;
    const int wid  = tid >> 5;
    const int b    = blockIdx.x;
    const int isbyte = (((const int*)maskp)[0] == 0x01010101);
    const long mbase = (long)b * T_;

    // bulk preload (coalesced float4)
    {
        const float4* src = (const float4*)(g_eexp + mbase * C_);
        float4* dst = (float4*)sEE;
        for (int i = tid; i < (T_ * C_) / 4; i += 128) dst[i] = src[i];
        const float4* s2 = (const float4*)(g_em0 + mbase);
        float4* d2 = (float4*)sEM0;
        for (int i = tid; i < T_ / 4; i += 128) d2[i] = s2[i];
    }
    for (int i = tid; i < 400; i += 128) sT[i] = trans[i];

    // length (mask is a monotone prefix)
    int lcnt = 0;
    for (int t = tid; t < T_; t += 128)
        lcnt += (load_mask(maskp, mbase + t, isbyte) != 0);
    for (int o = 16; o; o >>= 1) lcnt += __shfl_xor_sync(0xffffffffu, lcnt, o);
    if (lane == 0) sPart[4 + wid] = (float)lcnt;
    __syncthreads();
    const int len = (int)(sPart[4] + sPart[5] + sPart[6] + sPart[7]);

    const float* lg = logits + mbase * C_;

    if (wid == 0) {
        // ---- forward scan (warp 0) ----
        float Ecol[20];
#pragma unroll
        for (int i = 0; i < 20; i++)
            Ecol[i] = (lane < 20) ? __expf(sT[i * 20 + lane]) : 0.0f;

        float u = (lane < 20) ? sEE[lane] : 0.0f;
        float L = sEM0[0];

        for (int t = 1; t < len; t++) {
            float eeC  = (lane < 20) ? sEE[t * C_ + lane] : 0.0f;
            float em0C = sEM0[t];
            float s0 = 0.f, s1 = 0.f, s2 = 0.f, s3 = 0.f;
#pragma unroll
            for (int i = 0; i < 20; i += 4) {
                s0 = fmaf(__shfl_sync(0xffffffffu, u, i + 0), Ecol[i + 0], s0);
                s1 = fmaf(__shfl_sync(0xffffffffu, u, i + 1), Ecol[i + 1], s1);
                s2 = fmaf(__shfl_sync(0xffffffffu, u, i + 2), Ecol[i + 2], s2);
                s3 = fmaf(__shfl_sync(0xffffffffu, u, i + 3), Ecol[i + 3], s3);
            }
            u = eeC * ((s0 + s1) + (s2 + s3));
            L += em0C;
            if ((t & 3) == 0) {                 // rescale; log off the chain
                float k = __shfl_sync(0xffffffffu, u, 0);
                u *= __fdividef(1.0f, k);
                L += __logf(k);
            }
        }
        float e = u;
        for (int o = 16; o; o >>= 1) e += __shfl_xor_sync(0xffffffffu, e, o);
        if (lane == 0) sPart[0] = L + __logf(e);     // log_den
    } else {
        // ---- log_num (warps 1-3, 96 threads) ----
        const int id = tid - 32;
        float sn = 0.0f;
        for (int t = id; t < len; t += 96)
            sn += lg[t * C_ + tags[mbase + t]];
        for (int t = id; t < len - 1; t += 96)
            sn += sT[tags[mbase + t] * 20 + tags[mbase + t + 1]];
        for (int o = 16; o; o >>= 1) sn += __shfl_xor_sync(0xffffffffu, sn, o);
        if (lane == 0) sPart[wid] = sn;
    }
    __syncthreads();
    if (tid == 0)
        g_res[b] = sPart[0] - (sPart[1] + sPart[2] + sPart[3]);
}

// Kernel 5: deterministic mean over batches -> loss
__global__ void k_final(float* __restrict__ out)
{
    const int lane = threadIdx.x;
    float v = g_res[lane] + g_res[lane + 32];
    for (int o = 16; o; o >>= 1) v += __shfl_xor_sync(0xffffffffu, v, o);
    if (lane == 0) out[0] = v * (1.0f / 64.0f);
}

// ==========================================================================
extern "C" void kernel_launch(void* const* d_in, const int* in_sizes, int n_in,
                              void* d_out, int out_size)
{
    const int*   x      = (const int*)  d_in[0];
    const void*  mask   =               d_in[1];
    const int*   tags   = (const int*)  d_in[2];
    const float* emb    = (const float*)d_in[3];
    const float* W_ih_f = (const float*)d_in[4];
    const float* W_hh_f = (const float*)d_in[5];
    const float* b_ih_f = (const float*)d_in[6];
    const float* b_hh_f = (const float*)d_in[7];
    const float* W_ih_b = (const float*)d_in[8];
    const float* W_hh_b = (const float*)d_in[9];
    const float* b_ih_b = (const float*)d_in[10];
    const float* b_hh_b = (const float*)d_in[11];
    const float* fc_W   = (const float*)d_in[12];
    const float* fc_b   = (const float*)d_in[13];
    const float* trans  = (const float*)d_in[14];

    float* out        = (float*)d_out;
    float* loss_ptr   = out;
    float* logits_ptr = out + 1;
    if (out_size == BT_ * C_) {
        logits_ptr = out;
        loss_ptr   = nullptr;
    }

    k_input_gemm<<<dim3(8, 256), 256>>>(x, emb, W_ih_f, W_ih_b,
                                        b_ih_f, b_hh_f, b_ih_b, b_hh_b);
    k_lstm<<<128, 256>>>(W_hh_f, W_hh_b);
    k_logits<<<BT_ / 16, 256>>>(fc_W, fc_b, logits_ptr);
    k_crf<<<B_, 128>>>(logits_ptr, tags, mask, trans);
    if (loss_ptr) k_final<<<1, 32>>>(loss_ptr);
}

// round 6
// speedup vs baseline: 1.3282x; 1.3282x over previous
#include <cuda_runtime.h>
#include <cuda_fp16.h>
#include <cstdint>

#define B_   64
#define T_   512
#define H_   128
#define E_   300
#define C_   20
#define G4_  512
#define BT_  (B_ * T_)          // 32768

// -------- scratch (static device globals; no runtime allocation) -----------
__device__ __align__(16) float g_xw[2u * BT_ * G4_];   // 128 MB
__device__ __align__(16) float g_h [(unsigned)BT_ * 2 * H_];  // 32 MB
__device__ __align__(16) float g_eexp[(unsigned)BT_ * C_];    // exp(em_j - em_0)
__device__ float g_em0[BT_];
__device__ float g_res[B_];

// ----------------------------- math helpers --------------------------------
__device__ __forceinline__ float fast_sigmoid(float x) {
    return __fdividef(1.0f, 1.0f + __expf(-x));
}
__device__ __forceinline__ float fast_tanh(float x) {
    float ax = fabsf(x);
    float e  = __expf(-2.0f * ax);
    float t  = __fdividef(1.0f - e, 1.0f + e);
    return copysignf(t, x);
}
__device__ __forceinline__ int load_mask(const void* m, long idx, int isbyte) {
    return isbyte ? (int)((const unsigned char*)m)[idx] : ((const int*)m)[idx];
}
__device__ __forceinline__ float2 ffma2(float2 a, float2 b, float2 c) {
    unsigned long long ua = *reinterpret_cast<unsigned long long*>(&a);
    unsigned long long ub = *reinterpret_cast<unsigned long long*>(&b);
    unsigned long long uc = *reinterpret_cast<unsigned long long*>(&c);
    unsigned long long ud;
    asm("fma.rn.f32x2 %0, %1, %2, %3;" : "=l"(ud) : "l"(ua), "l"(ub), "l"(uc));
    return *reinterpret_cast<float2*>(&ud);
}

// ==========================================================================
// Kernel 1: fused embedding gather + input GEMM, register double-buffered.
// ==========================================================================
__global__ void __launch_bounds__(256, 2) k_input_gemm(
    const int*   __restrict__ x,
    const float* __restrict__ emb,
    const float* __restrict__ Wf,  const float* __restrict__ Wb,
    const float* __restrict__ bif, const float* __restrict__ bhf,
    const float* __restrict__ bib, const float* __restrict__ bhb)
{
    __shared__ __align__(16) float sA[16][128];
    __shared__ __align__(16) float sB[16][128];
    __shared__ int sIdx[128];

    const int tid   = threadIdx.x;
    const int m0    = blockIdx.y * 128;
    const int n0    = blockIdx.x * 128;
    const int dir   = n0 >> 9;
    const int gbase = n0 & 511;
    const float* W  = dir ? Wb : Wf;

    if (tid < 128) sIdx[tid] = x[m0 + tid];
    __syncthreads();

    const int row0 = (tid * 2)     >> 2, q0 = (tid * 2)     & 3;
    const int row1 = (tid * 2 + 1) >> 2, q1 = (tid * 2 + 1) & 3;
    const long arow0 = (long)sIdx[row0] * 300, arow1 = (long)sIdx[row1] * 300;
    const long brow0 = (long)(gbase + row0) * 300, brow1 = (long)(gbase + row1) * 300;

    float2 acc[8][4];
#pragma unroll
    for (int i = 0; i < 8; i++)
#pragma unroll
        for (int j = 0; j < 4; j++) acc[i][j] = make_float2(0.f, 0.f);

    const int tm0 = (tid >> 4) << 3;
    const int tn0 = (tid & 15) << 3;

    float4 va0, va1, vb0, vb1;
    {
        int kg0 = 4 * q0, kg1 = 4 * q1;
        va0 = *(const float4*)(emb + arow0 + kg0);
        vb0 = *(const float4*)(W   + brow0 + kg0);
        va1 = *(const float4*)(emb + arow1 + kg1);
        vb1 = *(const float4*)(W   + brow1 + kg1);
    }

    for (int ks = 0; ks < 19; ks++) {
        sA[4*q0+0][row0] = va0.x; sA[4*q0+1][row0] = va0.y;
        sA[4*q0+2][row0] = va0.z; sA[4*q0+3][row0] = va0.w;
        sB[4*q0+0][row0] = vb0.x; sB[4*q0+1][row0] = vb0.y;
        sB[4*q0+2][row0] = vb0.z; sB[4*q0+3][row0] = vb0.w;
        sA[4*q1+0][row1] = va1.x; sA[4*q1+1][row1] = va1.y;
        sA[4*q1+2][row1] = va1.z; sA[4*q1+3][row1] = va1.w;
        sB[4*q1+0][row1] = vb1.x; sB[4*q1+1][row1] = vb1.y;
        sB[4*q1+2][row1] = vb1.z; sB[4*q1+3][row1] = vb1.w;
        __syncthreads();

        if (ks < 18) {
            int k0  = (ks + 1) * 16;
            int kg0 = k0 + 4 * q0, kg1 = k0 + 4 * q1;
            if (kg0 < 300) {
                va0 = *(const float4*)(emb + arow0 + kg0);
                vb0 = *(const float4*)(W   + brow0 + kg0);
            } else { va0 = make_float4(0,0,0,0); vb0 = make_float4(0,0,0,0); }
            if (kg1 < 300) {
                va1 = *(const float4*)(emb + arow1 + kg1);
                vb1 = *(const float4*)(W   + brow1 + kg1);
            } else { va1 = make_float4(0,0,0,0); vb1 = make_float4(0,0,0,0); }
        }

#pragma unroll
        for (int kk = 0; kk < 16; kk++) {
            float a[8];
            float2 b2[4];
            *(float4*)(a)     = *(const float4*)&sA[kk][tm0];
            *(float4*)(a + 4) = *(const float4*)&sA[kk][tm0 + 4];
            *(float2*)(&b2[0]) = *(const float2*)&sB[kk][tn0];
            *(float2*)(&b2[1]) = *(const float2*)&sB[kk][tn0 + 2];
            *(float2*)(&b2[2]) = *(const float2*)&sB[kk][tn0 + 4];
            *(float2*)(&b2[3]) = *(const float2*)&sB[kk][tn0 + 6];
#pragma unroll
            for (int i = 0; i < 8; i++) {
                float2 ai = make_float2(a[i], a[i]);
#pragma unroll
                for (int j = 0; j < 4; j++)
                    acc[i][j] = ffma2(ai, b2[j], acc[i][j]);
            }
        }
        __syncthreads();
    }

    const float* bi = dir ? bib : bif;
    const float* bh = dir ? bhb : bhf;
    float bias[8];
#pragma unroll
    for (int j = 0; j < 8; j++) {
        int g = gbase + tn0 + j;
        bias[j] = bi[g] + bh[g];
    }
    float* outbase = g_xw + (long)dir * BT_ * G4_;
#pragma unroll
    for (int i = 0; i < 8; i++) {
        long rowoff = (long)(m0 + tm0 + i) * G4_ + gbase + tn0;
        float4 o0 = make_float4(acc[i][0].x + bias[0], acc[i][0].y + bias[1],
                                acc[i][1].x + bias[2], acc[i][1].y + bias[3]);
        float4 o1 = make_float4(acc[i][2].x + bias[4], acc[i][2].y + bias[5],
                                acc[i][3].x + bias[6], acc[i][3].y + bias[7]);
        *(float4*)(outbase + rowoff)     = o0;
        *(float4*)(outbase + rowoff + 4) = o1;
    }
}

// ==========================================================================
// Kernel 2: LSTM recurrence — HYBRID weight residency.
//   k = 0..63  -> registers (64 unsigned = half2 pairs; no spill risk)
//   k = 64..127-> smem uint4 (64 KB; crossbar halved vs full-smem version)
// ==========================================================================
__global__ void __launch_bounds__(256) k_lstm(
    const float* __restrict__ Whf, const float* __restrict__ Whb)
{
    extern __shared__ __align__(16) char smem[];
    uint4* sWs = (uint4*)smem;                      // 16*256*16 = 65536 B
    float* sh  = (float*)(smem + 65536);            // h[128]
    float* sg  = sh + 128;                          // gates[512]

    const int tid = threadIdx.x;
    const int dir = blockIdx.x >> 6;
    const int b   = blockIdx.x & 63;
    const float* Wh = dir ? Whb : Whf;

    // smem part: k = 64..127, layout sWs[p4][col] (p4 = (k-64)/4)
    for (int idx = tid; idx < 16 * 256; idx += 256) {
        int p4  = idx >> 8;            // 0..15
        int col = idx & 255;
        int g0  = col * 2;
        int k0  = 64 + 4 * p4;
        float4 w0 = *(const float4*)(Wh + (long)(g0    ) * 128 + k0);
        float4 w1 = *(const float4*)(Wh + (long)(g0 + 1) * 128 + k0);
        __half2 t0 = __floats2half2_rn(w0.x, w0.y);
        __half2 t1 = __floats2half2_rn(w1.x, w1.y);
        __half2 t2 = __floats2half2_rn(w0.z, w0.w);
        __half2 t3 = __floats2half2_rn(w1.z, w1.w);
        uint4 u;
        u.x = *(unsigned*)&t0; u.y = *(unsigned*)&t1;
        u.z = *(unsigned*)&t2; u.w = *(unsigned*)&t3;
        sWs[p4 * 256 + col] = u;
    }
    // register part: k = 0..63 for gates 2*tid, 2*tid+1
    unsigned wA[32], wB[32];
    {
        const float2* r0 = (const float2*)(Wh + (long)(2 * tid)     * 128);
        const float2* r1 = (const float2*)(Wh + (long)(2 * tid + 1) * 128);
#pragma unroll
        for (int p = 0; p < 32; p++) {             // k = 2p, 2p+1
            float2 a = r0[p], bb = r1[p];
            __half2 ha = __floats2half2_rn(a.x, a.y);
            __half2 hb = __floats2half2_rn(bb.x, bb.y);
            wA[p] = *(unsigned*)&ha;
            wB[p] = *(unsigned*)&hb;
        }
    }
    if (tid < 128) sh[tid] = 0.0f;
    float c = 0.0f;
    __syncthreads();

    const float* xwp = g_xw + (long)dir * BT_ * G4_ + (long)b * T_ * G4_;
    float* hout = g_h + (long)b * T_ * (2 * H_) + (dir ? H_ : 0);
    const float4* sh4 = (const float4*)sh;

    int t  = dir ? (T_ - 1) : 0;
    const int dt = dir ? -1 : 1;
    const int sec = tid >> 6;   // 0:i 1:f 2:g(tanh) 3:o

    float2 xv_next = *(const float2*)(xwp + (long)t * G4_ + 2 * tid);

    for (int s = 0; s < T_; s++, t += dt) {
        float2 xv = xv_next;
        if (s + 1 < T_)
            xv_next = *(const float2*)(xwp + (long)(t + dt) * G4_ + 2 * tid);

        float2 accA = make_float2(xv.x, 0.0f);
        float2 accB = make_float2(xv.y, 0.0f);
        // k = 0..63 from registers
#pragma unroll
        for (int p4 = 0; p4 < 16; p4++) {
            float4 h4 = sh4[p4];
            float2 h01 = make_float2(h4.x, h4.y);
            float2 h23 = make_float2(h4.z, h4.w);
            accA = ffma2(__half22float2(*(__half2*)&wA[2*p4]),     h01, accA);
            accB = ffma2(__half22float2(*(__half2*)&wB[2*p4]),     h01, accB);
            accA = ffma2(__half22float2(*(__half2*)&wA[2*p4 + 1]), h23, accA);
            accB = ffma2(__half22float2(*(__half2*)&wB[2*p4 + 1]), h23, accB);
        }
        // k = 64..127 from smem
#pragma unroll
        for (int p4 = 0; p4 < 16; p4++) {
            float4 h4 = sh4[16 + p4];
            uint4  u  = sWs[p4 * 256 + tid];
            float2 h01 = make_float2(h4.x, h4.y);
            float2 h23 = make_float2(h4.z, h4.w);
            accA = ffma2(__half22float2(*(__half2*)&u.x), h01, accA);
            accB = ffma2(__half22float2(*(__half2*)&u.y), h01, accB);
            accA = ffma2(__half22float2(*(__half2*)&u.z), h23, accA);
            accB = ffma2(__half22float2(*(__half2*)&u.w), h23, accB);
        }
        float gA = accA.x + accA.y;
        float gB = accB.x + accB.y;
        if (sec == 2) { gA = fast_tanh(gA);    gB = fast_tanh(gB); }
        else          { gA = fast_sigmoid(gA); gB = fast_sigmoid(gB); }
        *(float2*)(sg + 2 * tid) = make_float2(gA, gB);
        __syncthreads();
        if (tid < 128) {
            float cc = fmaf(sg[128 + tid], c, sg[tid] * sg[256 + tid]);
            c = cc;
            float hv = sg[384 + tid] * fast_tanh(cc);
            sh[tid] = hv;
            hout[(long)t * (2 * H_) + tid] = hv;
        }
        __syncthreads();
    }
}

// ==========================================================================
// Kernel 3: logits + CRF emission precompute.
// ==========================================================================
__global__ void __launch_bounds__(256) k_logits(
    const float* __restrict__ fcW, const float* __restrict__ fcb,
    float* __restrict__ logits)
{
    __shared__ float sW[20 * 257];
    __shared__ float shh[16 * 257];
    __shared__ float sl[16 * 20];
    const int tid = threadIdx.x;
    const long bt0 = (long)blockIdx.x * 16;

    for (int i = tid; i < 20 * 256; i += 256) {
        int cc = i >> 8, k = i & 255;
        sW[cc * 257 + k] = fcW[i];
    }
    for (int i = tid; i < 16 * 256; i += 256) {
        int tk = i >> 8, k = i & 255;
        shh[tk * 257 + k] = g_h[(bt0 + tk) * 256 + k];
    }
    __syncthreads();
    for (int o = tid; o < 16 * 20; o += 256) {
        int tk = o / 20, cc = o % 20;
        const float* hr = shh + tk * 257;
        const float* wr = sW  + cc * 257;
        float a0 = 0.f, a1 = 0.f, a2 = 0.f, a3 = 0.f;
#pragma unroll 16
        for (int k = 0; k < 256; k += 4) {
            a0 = fmaf(hr[k + 0], wr[k + 0], a0);
            a1 = fmaf(hr[k + 1], wr[k + 1], a1);
            a2 = fmaf(hr[k + 2], wr[k + 2], a2);
            a3 = fmaf(hr[k + 3], wr[k + 3], a3);
        }
        float lv = fcb[cc] + ((a0 + a1) + (a2 + a3));
        sl[o] = lv;
        logits[(bt0 + tk) * C_ + cc] = lv;
    }
    __syncthreads();
    for (int o = tid; o < 16 * 20; o += 256) {
        int tk = o / 20, cc = o % 20;
        g_eexp[(bt0 + tk) * C_ + cc] = __expf(sl[o] - sl[tk * 20]);
        if (cc == 0) g_em0[bt0 + tk] = sl[tk * 20];
    }
}

// ==========================================================================
// Kernel 4: CRF — exp-space scan from SMEM-resident tables (R5 version).
// ==========================================================================
__global__ void __launch_bounds__(128) k_crf(
    const float* __restrict__ logits,
    const int*   __restrict__ tags,
    const void*  __restrict__ maskp,
    const float* __restrict__ trans)
{
    __shared__ __align__(16) float sEE[T_ * C_];   // 40960 B
    __shared__ __align__(16) float sEM0[T_];       // 2048 B
    __shared__ float sT[400];
    __shared__ float sPart[8];
    const int tid  = threadIdx.x;
    const int lane = tid & 31;
    const int wid  = tid >> 5;
    const int b    = blockIdx.x;
    const int isbyte = (((const int*)maskp)[0] == 0x01010101);
    const long mbase = (long)b * T_;

    {
        const float4* src = (const float4*)(g_eexp + mbase * C_);
        float4* dst = (float4*)sEE;
        for (int i = tid; i < (T_ * C_) / 4; i += 128) dst[i] = src[i];
        const float4* s2 = (const float4*)(g_em0 + mbase);
        float4* d2 = (float4*)sEM0;
        for (int i = tid; i < T_ / 4; i += 128) d2[i] = s2[i];
    }
    for (int i = tid; i < 400; i += 128) sT[i] = trans[i];

    int lcnt = 0;
    for (int t = tid; t < T_; t += 128)
        lcnt += (load_mask(maskp, mbase + t, isbyte) != 0);
    for (int o = 16; o; o >>= 1) lcnt += __shfl_xor_sync(0xffffffffu, lcnt, o);
    if (lane == 0) sPart[4 + wid] = (float)lcnt;
    __syncthreads();
    const int len = (int)(sPart[4] + sPart[5] + sPart[6] + sPart[7]);

    const float* lg = logits + mbase * C_;

    if (wid == 0) {
        float Ecol[20];
#pragma unroll
        for (int i = 0; i < 20; i++)
            Ecol[i] = (lane < 20) ? __expf(sT[i * 20 + lane]) : 0.0f;

        float u = (lane < 20) ? sEE[lane] : 0.0f;
        float L = sEM0[0];

        for (int t = 1; t < len; t++) {
            float eeC  = (lane < 20) ? sEE[t * C_ + lane] : 0.0f;
            float em0C = sEM0[t];
            float s0 = 0.f, s1 = 0.f, s2 = 0.f, s3 = 0.f;
#pragma unroll
            for (int i = 0; i < 20; i += 4) {
                s0 = fmaf(__shfl_sync(0xffffffffu, u, i + 0), Ecol[i + 0], s0);
                s1 = fmaf(__shfl_sync(0xffffffffu, u, i + 1), Ecol[i + 1], s1);
                s2 = fmaf(__shfl_sync(0xffffffffu, u, i + 2), Ecol[i + 2], s2);
                s3 = fmaf(__shfl_sync(0xffffffffu, u, i + 3), Ecol[i + 3], s3);
            }
            u = eeC * ((s0 + s1) + (s2 + s3));
            L += em0C;
            if ((t & 3) == 0) {
                float k = __shfl_sync(0xffffffffu, u, 0);
                u *= __fdividef(1.0f, k);
                L += __logf(k);
            }
        }
        float e = u;
        for (int o = 16; o; o >>= 1) e += __shfl_xor_sync(0xffffffffu, e, o);
        if (lane == 0) sPart[0] = L + __logf(e);
    } else {
        const int id = tid - 32;
        float sn = 0.0f;
        for (int t = id; t < len; t += 96)
            sn += lg[t * C_ + tags[mbase + t]];
        for (int t = id; t < len - 1; t += 96)
            sn += sT[tags[mbase + t] * 20 + tags[mbase + t + 1]];
        for (int o = 16; o; o >>= 1) sn += __shfl_xor_sync(0xffffffffu, sn, o);
        if (lane == 0) sPart[wid] = sn;
    }
    __syncthreads();
    if (tid == 0)
        g_res[b] = sPart[0] - (sPart[1] + sPart[2] + sPart[3]);
}

// Kernel 5: deterministic mean over batches -> loss
__global__ void k_final(float* __restrict__ out)
{
    const int lane = threadIdx.x;
    float v = g_res[lane] + g_res[lane + 32];
    for (int o = 16; o; o >>= 1) v += __shfl_xor_sync(0xffffffffu, v, o);
    if (lane == 0) out[0] = v * (1.0f / 64.0f);
}

// ==========================================================================
extern "C" void kernel_launch(void* const* d_in, const int* in_sizes, int n_in,
                              void* d_out, int out_size)
{
    const int*   x      = (const int*)  d_in[0];
    const void*  mask   =               d_in[1];
    const int*   tags   = (const int*)  d_in[2];
    const float* emb    = (const float*)d_in[3];
    const float* W_ih_f = (const float*)d_in[4];
    const float* W_hh_f = (const float*)d_in[5];
    const float* b_ih_f = (const float*)d_in[6];
    const float* b_hh_f = (const float*)d_in[7];
    const float* W_ih_b = (const float*)d_in[8];
    const float* W_hh_b = (const float*)d_in[9];
    const float* b_ih_b = (const float*)d_in[10];
    const float* b_hh_b = (const float*)d_in[11];
    const float* fc_W   = (const float*)d_in[12];
    const float* fc_b   = (const float*)d_in[13];
    const float* trans  = (const float*)d_in[14];

    float* out        = (float*)d_out;
    float* loss_ptr   = out;
    float* logits_ptr = out + 1;
    if (out_size == BT_ * C_) {
        logits_ptr = out;
        loss_ptr   = nullptr;
    }

    const int lstm_smem = 65536 + 128 * 4 + 512 * 4;   // 68096 B
    cudaFuncSetAttribute(k_lstm, cudaFuncAttributeMaxDynamicSharedMemorySize,
                         lstm_smem);

    k_input_gemm<<<dim3(8, 256), 256>>>(x, emb, W_ih_f, W_ih_b,
                                        b_ih_f, b_hh_f, b_ih_b, b_hh_b);
    k_lstm<<<128, 256, lstm_smem>>>(W_hh_f, W_hh_b);
    k_logits<<<BT_ / 16, 256>>>(fc_W, fc_b, logits_ptr);
    k_crf<<<B_, 128>>>(logits_ptr, tags, mask, trans);
    if (loss_ptr) k_final<<<1, 32>>>(loss_ptr);
}

// round 7
// speedup vs baseline: 1.4389x; 1.0834x over previous
#include <cuda_runtime.h>
#include <cuda_fp16.h>
#include <cstdint>

#define B_   64
#define T_   512
#define H_   128
#define E_   300
#define C_   20
#define G4_  512
#define BT_  (B_ * T_)          // 32768

// -------- scratch (static device globals; no runtime allocation) -----------
__device__ __align__(16) float g_xw[2u * BT_ * G4_];   // 128 MB
__device__ __align__(16) float g_h [(unsigned)BT_ * 2 * H_];  // 32 MB
__device__ __align__(16) float g_eexp[(unsigned)BT_ * C_];    // exp(em_j - em_0)
__device__ float g_em0[BT_];
__device__ float g_res[B_];

// ----------------------------- math helpers --------------------------------
__device__ __forceinline__ float fast_sigmoid(float x) {
    return __fdividef(1.0f, 1.0f + __expf(-x));
}
__device__ __forceinline__ float fast_tanh(float x) {
    float ax = fabsf(x);
    float e  = __expf(-2.0f * ax);
    float t  = __fdividef(1.0f - e, 1.0f + e);
    return copysignf(t, x);
}
__device__ __forceinline__ int load_mask(const void* m, long idx, int isbyte) {
    return isbyte ? (int)((const unsigned char*)m)[idx] : ((const int*)m)[idx];
}
__device__ __forceinline__ float2 ffma2(float2 a, float2 b, float2 c) {
    unsigned long long ua = *reinterpret_cast<unsigned long long*>(&a);
    unsigned long long ub = *reinterpret_cast<unsigned long long*>(&b);
    unsigned long long uc = *reinterpret_cast<unsigned long long*>(&c);
    unsigned long long ud;
    asm("fma.rn.f32x2 %0, %1, %2, %3;" : "=l"(ud) : "l"(ua), "l"(ub), "l"(uc));
    return *reinterpret_cast<float2*>(&ud);
}

// ==========================================================================
// Kernel 1: fused embedding gather + input GEMM.
//   BM=128 BN=128 BK=16, 8x8/thread via FFMA2.
//   - B fragments: strided column pairs n = 32*jj + 2*q (q=tid&15) so the
//     16 distinct LDS.64 addresses hit banks 0,2,..,30 (conflict-free; the
//     old contiguous octet mapping was 4-way conflicted on banks 0/8/16/24).
//   - Double-buffered smem: one __syncthreads per k-slice; LDG(next) issues
//     before compute(cur), STS(next) after compute into the idle buffer.
// ==========================================================================
__global__ void __launch_bounds__(256, 2) k_input_gemm(
    const int*   __restrict__ x,
    const float* __restrict__ emb,
    const float* __restrict__ Wf,  const float* __restrict__ Wb,
    const float* __restrict__ bif, const float* __restrict__ bhf,
    const float* __restrict__ bib, const float* __restrict__ bhb)
{
    __shared__ __align__(16) float sA[2][16][128];
    __shared__ __align__(16) float sB[2][16][128];
    __shared__ int sIdx[128];

    const int tid   = threadIdx.x;
    const int m0    = blockIdx.y * 128;
    const int n0    = blockIdx.x * 128;
    const int dir   = n0 >> 9;
    const int gbase = n0 & 511;
    const float* W  = dir ? Wb : Wf;

    if (tid < 128) sIdx[tid] = x[m0 + tid];
    __syncthreads();

    const int row0 = (tid * 2)     >> 2, q0 = (tid * 2)     & 3;
    const int row1 = (tid * 2 + 1) >> 2, q1 = (tid * 2 + 1) & 3;
    const long arow0 = (long)sIdx[row0] * 300, arow1 = (long)sIdx[row1] * 300;
    const long brow0 = (long)(gbase + row0) * 300, brow1 = (long)(gbase + row1) * 300;

    float2 acc[8][4];
#pragma unroll
    for (int i = 0; i < 8; i++)
#pragma unroll
        for (int j = 0; j < 4; j++) acc[i][j] = make_float2(0.f, 0.f);

    const int tm0 = (tid >> 4) << 3;       // 8 M-rows, contiguous
    const int q   = tid & 15;              // N pairs at 32*jj + 2*q

    float4 va0, va1, vb0, vb1;
    {   // prologue: slice 0
        int kg0 = 4 * q0, kg1 = 4 * q1;
        va0 = *(const float4*)(emb + arow0 + kg0);
        vb0 = *(const float4*)(W   + brow0 + kg0);
        va1 = *(const float4*)(emb + arow1 + kg1);
        vb1 = *(const float4*)(W   + brow1 + kg1);
        sA[0][4*q0+0][row0] = va0.x; sA[0][4*q0+1][row0] = va0.y;
        sA[0][4*q0+2][row0] = va0.z; sA[0][4*q0+3][row0] = va0.w;
        sB[0][4*q0+0][row0] = vb0.x; sB[0][4*q0+1][row0] = vb0.y;
        sB[0][4*q0+2][row0] = vb0.z; sB[0][4*q0+3][row0] = vb0.w;
        sA[0][4*q1+0][row1] = va1.x; sA[0][4*q1+1][row1] = va1.y;
        sA[0][4*q1+2][row1] = va1.z; sA[0][4*q1+3][row1] = va1.w;
        sB[0][4*q1+0][row1] = vb1.x; sB[0][4*q1+1][row1] = vb1.y;
        sB[0][4*q1+2][row1] = vb1.z; sB[0][4*q1+3][row1] = vb1.w;
    }
    __syncthreads();

    for (int ks = 0; ks < 19; ks++) {
        const int cur = ks & 1;
        const int nxt = cur ^ 1;

        if (ks < 18) {   // issue next slice's LDG before compute
            int k0  = (ks + 1) * 16;
            int kg0 = k0 + 4 * q0, kg1 = k0 + 4 * q1;
            if (kg0 < 300) {
                va0 = *(const float4*)(emb + arow0 + kg0);
                vb0 = *(const float4*)(W   + brow0 + kg0);
            } else { va0 = make_float4(0,0,0,0); vb0 = make_float4(0,0,0,0); }
            if (kg1 < 300) {
                va1 = *(const float4*)(emb + arow1 + kg1);
                vb1 = *(const float4*)(W   + brow1 + kg1);
            } else { va1 = make_float4(0,0,0,0); vb1 = make_float4(0,0,0,0); }
        }

#pragma unroll
        for (int kk = 0; kk < 16; kk++) {
            float a[8];
            float2 b2[4];
            *(float4*)(a)     = *(const float4*)&sA[cur][kk][tm0];
            *(float4*)(a + 4) = *(const float4*)&sA[cur][kk][tm0 + 4];
#pragma unroll
            for (int jj = 0; jj < 4; jj++)        // conflict-free LDS.64
                b2[jj] = *(const float2*)&sB[cur][kk][32 * jj + 2 * q];
#pragma unroll
            for (int i = 0; i < 8; i++) {
                float2 ai = make_float2(a[i], a[i]);
#pragma unroll
                for (int jj = 0; jj < 4; jj++)
                    acc[i][jj] = ffma2(ai, b2[jj], acc[i][jj]);
            }
        }

        if (ks < 18) {   // stage next slice into the idle buffer
            sA[nxt][4*q0+0][row0] = va0.x; sA[nxt][4*q0+1][row0] = va0.y;
            sA[nxt][4*q0+2][row0] = va0.z; sA[nxt][4*q0+3][row0] = va0.w;
            sB[nxt][4*q0+0][row0] = vb0.x; sB[nxt][4*q0+1][row0] = vb0.y;
            sB[nxt][4*q0+2][row0] = vb0.z; sB[nxt][4*q0+3][row0] = vb0.w;
            sA[nxt][4*q1+0][row1] = va1.x; sA[nxt][4*q1+1][row1] = va1.y;
            sA[nxt][4*q1+2][row1] = va1.z; sA[nxt][4*q1+3][row1] = va1.w;
            sB[nxt][4*q1+0][row1] = vb1.x; sB[nxt][4*q1+1][row1] = vb1.y;
            sB[nxt][4*q1+2][row1] = vb1.z; sB[nxt][4*q1+3][row1] = vb1.w;
            __syncthreads();
        }
    }

    const float* bi = dir ? bib : bif;
    const float* bh = dir ? bhb : bhf;
    float2 bias[4];
#pragma unroll
    for (int jj = 0; jj < 4; jj++) {
        int g = gbase + 32 * jj + 2 * q;
        bias[jj] = make_float2(bi[g] + bh[g], bi[g + 1] + bh[g + 1]);
    }
    float* outbase = g_xw + (long)dir * BT_ * G4_;
#pragma unroll
    for (int i = 0; i < 8; i++) {
        long rowoff = (long)(m0 + tm0 + i) * G4_ + gbase;
#pragma unroll
        for (int jj = 0; jj < 4; jj++) {
            float2 o = make_float2(acc[i][jj].x + bias[jj].x,
                                   acc[i][jj].y + bias[jj].y);
            *(float2*)(outbase + rowoff + 32 * jj + 2 * q) = o;
        }
    }
}

// ==========================================================================
// Kernel 2: LSTM recurrence — HYBRID weight residency (unchanged from R6).
// ==========================================================================
__global__ void __launch_bounds__(256) k_lstm(
    const float* __restrict__ Whf, const float* __restrict__ Whb)
{
    extern __shared__ __align__(16) char smem[];
    uint4* sWs = (uint4*)smem;                      // 16*256*16 = 65536 B
    float* sh  = (float*)(smem + 65536);            // h[128]
    float* sg  = sh + 128;                          // gates[512]

    const int tid = threadIdx.x;
    const int dir = blockIdx.x >> 6;
    const int b   = blockIdx.x & 63;
    const float* Wh = dir ? Whb : Whf;

    for (int idx = tid; idx < 16 * 256; idx += 256) {
        int p4  = idx >> 8;
        int col = idx & 255;
        int g0  = col * 2;
        int k0  = 64 + 4 * p4;
        float4 w0 = *(const float4*)(Wh + (long)(g0    ) * 128 + k0);
        float4 w1 = *(const float4*)(Wh + (long)(g0 + 1) * 128 + k0);
        __half2 t0 = __floats2half2_rn(w0.x, w0.y);
        __half2 t1 = __floats2half2_rn(w1.x, w1.y);
        __half2 t2 = __floats2half2_rn(w0.z, w0.w);
        __half2 t3 = __floats2half2_rn(w1.z, w1.w);
        uint4 u;
        u.x = *(unsigned*)&t0; u.y = *(unsigned*)&t1;
        u.z = *(unsigned*)&t2; u.w = *(unsigned*)&t3;
        sWs[p4 * 256 + col] = u;
    }
    unsigned wA[32], wB[32];
    {
        const float2* r0 = (const float2*)(Wh + (long)(2 * tid)     * 128);
        const float2* r1 = (const float2*)(Wh + (long)(2 * tid + 1) * 128);
#pragma unroll
        for (int p = 0; p < 32; p++) {
            float2 a = r0[p], bb = r1[p];
            __half2 ha = __floats2half2_rn(a.x, a.y);
            __half2 hb = __floats2half2_rn(bb.x, bb.y);
            wA[p] = *(unsigned*)&ha;
            wB[p] = *(unsigned*)&hb;
        }
    }
    if (tid < 128) sh[tid] = 0.0f;
    float c = 0.0f;
    __syncthreads();

    const float* xwp = g_xw + (long)dir * BT_ * G4_ + (long)b * T_ * G4_;
    float* hout = g_h + (long)b * T_ * (2 * H_) + (dir ? H_ : 0);
    const float4* sh4 = (const float4*)sh;

    int t  = dir ? (T_ - 1) : 0;
    const int dt = dir ? -1 : 1;
    const int sec = tid >> 6;

    float2 xv_next = *(const float2*)(xwp + (long)t * G4_ + 2 * tid);

    for (int s = 0; s < T_; s++, t += dt) {
        float2 xv = xv_next;
        if (s + 1 < T_)
            xv_next = *(const float2*)(xwp + (long)(t + dt) * G4_ + 2 * tid);

        float2 accA = make_float2(xv.x, 0.0f);
        float2 accB = make_float2(xv.y, 0.0f);
#pragma unroll
        for (int p4 = 0; p4 < 16; p4++) {
            float4 h4 = sh4[p4];
            float2 h01 = make_float2(h4.x, h4.y);
            float2 h23 = make_float2(h4.z, h4.w);
            accA = ffma2(__half22float2(*(__half2*)&wA[2*p4]),     h01, accA);
            accB = ffma2(__half22float2(*(__half2*)&wB[2*p4]),     h01, accB);
            accA = ffma2(__half22float2(*(__half2*)&wA[2*p4 + 1]), h23, accA);
            accB = ffma2(__half22float2(*(__half2*)&wB[2*p4 + 1]), h23, accB);
        }
#pragma unroll
        for (int p4 = 0; p4 < 16; p4++) {
            float4 h4 = sh4[16 + p4];
            uint4  u  = sWs[p4 * 256 + tid];
            float2 h01 = make_float2(h4.x, h4.y);
            float2 h23 = make_float2(h4.z, h4.w);
            accA = ffma2(__half22float2(*(__half2*)&u.x), h01, accA);
            accB = ffma2(__half22float2(*(__half2*)&u.y), h01, accB);
            accA = ffma2(__half22float2(*(__half2*)&u.z), h23, accA);
            accB = ffma2(__half22float2(*(__half2*)&u.w), h23, accB);
        }
        float gA = accA.x + accA.y;
        float gB = accB.x + accB.y;
        if (sec == 2) { gA = fast_tanh(gA);    gB = fast_tanh(gB); }
        else          { gA = fast_sigmoid(gA); gB = fast_sigmoid(gB); }
        *(float2*)(sg + 2 * tid) = make_float2(gA, gB);
        __syncthreads();
        if (tid < 128) {
            float cc = fmaf(sg[128 + tid], c, sg[tid] * sg[256 + tid]);
            c = cc;
            float hv = sg[384 + tid] * fast_tanh(cc);
            sh[tid] = hv;
            hout[(long)t * (2 * H_) + tid] = hv;
        }
        __syncthreads();
    }
}

// ==========================================================================
// Kernel 3: logits + CRF emission precompute (unchanged).
// ==========================================================================
__global__ void __launch_bounds__(256) k_logits(
    const float* __restrict__ fcW, const float* __restrict__ fcb,
    float* __restrict__ logits)
{
    __shared__ float sW[20 * 257];
    __shared__ float shh[16 * 257];
    __shared__ float sl[16 * 20];
    const int tid = threadIdx.x;
    const long bt0 = (long)blockIdx.x * 16;

    for (int i = tid; i < 20 * 256; i += 256) {
        int cc = i >> 8, k = i & 255;
        sW[cc * 257 + k] = fcW[i];
    }
    for (int i = tid; i < 16 * 256; i += 256) {
        int tk = i >> 8, k = i & 255;
        shh[tk * 257 + k] = g_h[(bt0 + tk) * 256 + k];
    }
    __syncthreads();
    for (int o = tid; o < 16 * 20; o += 256) {
        int tk = o / 20, cc = o % 20;
        const float* hr = shh + tk * 257;
        const float* wr = sW  + cc * 257;
        float a0 = 0.f, a1 = 0.f, a2 = 0.f, a3 = 0.f;
#pragma unroll 16
        for (int k = 0; k < 256; k += 4) {
            a0 = fmaf(hr[k + 0], wr[k + 0], a0);
            a1 = fmaf(hr[k + 1], wr[k + 1], a1);
            a2 = fmaf(hr[k + 2], wr[k + 2], a2);
            a3 = fmaf(hr[k + 3], wr[k + 3], a3);
        }
        float lv = fcb[cc] + ((a0 + a1) + (a2 + a3));
        sl[o] = lv;
        logits[(bt0 + tk) * C_ + cc] = lv;
    }
    __syncthreads();
    for (int o = tid; o < 16 * 20; o += 256) {
        int tk = o / 20, cc = o % 20;
        g_eexp[(bt0 + tk) * C_ + cc] = __expf(sl[o] - sl[tk * 20]);
        if (cc == 0) g_em0[bt0 + tk] = sl[tk * 20];
    }
}

// ==========================================================================
// Kernel 4: CRF — exp-space scan from SMEM-resident tables (unchanged).
// ==========================================================================
__global__ void __launch_bounds__(128) k_crf(
    const float* __restrict__ logits,
    const int*   __restrict__ tags,
    const void*  __restrict__ maskp,
    const float* __restrict__ trans)
{
    __shared__ __align__(16) float sEE[T_ * C_];
    __shared__ __align__(16) float sEM0[T_];
    __shared__ float sT[400];
    __shared__ float sPart[8];
    const int tid  = threadIdx.x;
    const int lane = tid & 31;
    const int wid  = tid >> 5;
    const int b    = blockIdx.x;
    const int isbyte = (((const int*)maskp)[0] == 0x01010101);
    const long mbase = (long)b * T_;

    {
        const float4* src = (const float4*)(g_eexp + mbase * C_);
        float4* dst = (float4*)sEE;
        for (int i = tid; i < (T_ * C_) / 4; i += 128) dst[i] = src[i];
        const float4* s2 = (const float4*)(g_em0 + mbase);
        float4* d2 = (float4*)sEM0;
        for (int i = tid; i < T_ / 4; i += 128) d2[i] = s2[i];
    }
    for (int i = tid; i < 400; i += 128) sT[i] = trans[i];

    int lcnt = 0;
    for (int t = tid; t < T_; t += 128)
        lcnt += (load_mask(maskp, mbase + t, isbyte) != 0);
    for (int o = 16; o; o >>= 1) lcnt += __shfl_xor_sync(0xffffffffu, lcnt, o);
    if (lane == 0) sPart[4 + wid] = (float)lcnt;
    __syncthreads();
    const int len = (int)(sPart[4] + sPart[5] + sPart[6] + sPart[7]);

    const float* lg = logits + mbase * C_;

    if (wid == 0) {
        float Ecol[20];
#pragma unroll
        for (int i = 0; i < 20; i++)
            Ecol[i] = (lane < 20) ? __expf(sT[i * 20 + lane]) : 0.0f;

        float u = (lane < 20) ? sEE[lane] : 0.0f;
        float L = sEM0[0];

        for (int t = 1; t < len; t++) {
            float eeC  = (lane < 20) ? sEE[t * C_ + lane] : 0.0f;
            float em0C = sEM0[t];
            float s0 = 0.f, s1 = 0.f, s2 = 0.f, s3 = 0.f;
#pragma unroll
            for (int i = 0; i < 20; i += 4) {
                s0 = fmaf(__shfl_sync(0xffffffffu, u, i + 0), Ecol[i + 0], s0);
                s1 = fmaf(__shfl_sync(0xffffffffu, u, i + 1), Ecol[i + 1], s1);
                s2 = fmaf(__shfl_sync(0xffffffffu, u, i + 2), Ecol[i + 2], s2);
                s3 = fmaf(__shfl_sync(0xffffffffu, u, i + 3), Ecol[i + 3], s3);
            }
            u = eeC * ((s0 + s1) + (s2 + s3));
            L += em0C;
            if ((t & 3) == 0) {
                float k = __shfl_sync(0xffffffffu, u, 0);
                u *= __fdividef(1.0f, k);
                L += __logf(k);
            }
        }
        float e = u;
        for (int o = 16; o; o >>= 1) e += __shfl_xor_sync(0xffffffffu, e, o);
        if (lane == 0) sPart[0] = L + __logf(e);
    } else {
        const int id = tid - 32;
        float sn = 0.0f;
        for (int t = id; t < len; t += 96)
            sn += lg[t * C_ + tags[mbase + t]];
        for (int t = id; t < len - 1; t += 96)
            sn += sT[tags[mbase + t] * 20 + tags[mbase + t + 1]];
        for (int o = 16; o; o >>= 1) sn += __shfl_xor_sync(0xffffffffu, sn, o);
        if (lane == 0) sPart[wid] = sn;
    }
    __syncthreads();
    if (tid == 0)
        g_res[b] = sPart[0] - (sPart[1] + sPart[2] + sPart[3]);
}

// Kernel 5: deterministic mean over batches -> loss
__global__ void k_final(float* __restrict__ out)
{
    const int lane = threadIdx.x;
    float v = g_res[lane] + g_res[lane + 32];
    for (int o = 16; o; o >>= 1) v += __shfl_xor_sync(0xffffffffu, v, o);
    if (lane == 0) out[0] = v * (1.0f / 64.0f);
}

// ==========================================================================
extern "C" void kernel_launch(void* const* d_in, const int* in_sizes, int n_in,
                              void* d_out, int out_size)
{
    const int*   x      = (const int*)  d_in[0];
    const void*  mask   =               d_in[1];
    const int*   tags   = (const int*)  d_in[2];
    const float* emb    = (const float*)d_in[3];
    const float* W_ih_f = (const float*)d_in[4];
    const float* W_hh_f = (const float*)d_in[5];
    const float* b_ih_f = (const float*)d_in[6];
    const float* b_hh_f = (const float*)d_in[7];
    const float* W_ih_b = (const float*)d_in[8];
    const float* W_hh_b = (const float*)d_in[9];
    const float* b_ih_b = (const float*)d_in[10];
    const float* b_hh_b = (const float*)d_in[11];
    const float* fc_W   = (const float*)d_in[12];
    const float* fc_b   = (const float*)d_in[13];
    const float* trans  = (const float*)d_in[14];

    float* out        = (float*)d_out;
    float* loss_ptr   = out;
    float* logits_ptr = out + 1;
    if (out_size == BT_ * C_) {
        logits_ptr = out;
        loss_ptr   = nullptr;
    }

    const int lstm_smem = 65536 + 128 * 4 + 512 * 4;   // 68096 B
    cudaFuncSetAttribute(k_lstm, cudaFuncAttributeMaxDynamicSharedMemorySize,
                         lstm_smem);

    k_input_gemm<<<dim3(8, 256), 256>>>(x, emb, W_ih_f, W_ih_b,
                                        b_ih_f, b_hh_f, b_ih_b, b_hh_b);
    k_lstm<<<128, 256, lstm_smem>>>(W_hh_f, W_hh_b);
    k_logits<<<BT_ / 16, 256>>>(fc_W, fc_b, logits_ptr);
    k_crf<<<B_, 128>>>(logits_ptr, tags, mask, trans);
    if (loss_ptr) k_final<<<1, 32>>>(loss_ptr);
}

// round 8
// speedup vs baseline: 1.9083x; 1.3262x over previous
#include <cuda_runtime.h>
#include <cuda_fp16.h>
#include <cstdint>

#define B_   64
#define T_   512
#define H_   128
#define E_   300
#define C_   20
#define G4_  512
#define BT_  (B_ * T_)          // 32768

// -------- scratch (static device globals; no runtime allocation) -----------
__device__ __align__(16) float g_xw[2u * BT_ * G4_];   // 128 MB
__device__ __align__(16) float g_h [(unsigned)BT_ * 2 * H_];  // 32 MB
__device__ __align__(16) float g_eexp[(unsigned)BT_ * C_];    // exp(em_j - em_0)
__device__ float g_em0[BT_];
__device__ float g_res[B_];

// ----------------------------- math helpers --------------------------------
__device__ __forceinline__ float fast_sigmoid(float x) {
    return __fdividef(1.0f, 1.0f + __expf(-x));
}
__device__ __forceinline__ float fast_tanh(float x) {
    float ax = fabsf(x);
    float e  = __expf(-2.0f * ax);
    float t  = __fdividef(1.0f - e, 1.0f + e);
    return copysignf(t, x);
}
__device__ __forceinline__ int load_mask(const void* m, long idx, int isbyte) {
    return isbyte ? (int)((const unsigned char*)m)[idx] : ((const int*)m)[idx];
}
__device__ __forceinline__ float2 ffma2(float2 a, float2 b, float2 c) {
    unsigned long long ua = *reinterpret_cast<unsigned long long*>(&a);
    unsigned long long ub = *reinterpret_cast<unsigned long long*>(&b);
    unsigned long long uc = *reinterpret_cast<unsigned long long*>(&c);
    unsigned long long ud;
    asm("fma.rn.f32x2 %0, %1, %2, %3;" : "=l"(ud) : "l"(ua), "l"(ub), "l"(uc));
    return *reinterpret_cast<float2*>(&ud);
}
__device__ __forceinline__ void ldsm4(unsigned& r0, unsigned& r1,
                                      unsigned& r2, unsigned& r3,
                                      unsigned addr) {
    asm volatile("ldmatrix.sync.aligned.m8n8.x4.shared.b16 {%0,%1,%2,%3}, [%4];"
                 : "=r"(r0), "=r"(r1), "=r"(r2), "=r"(r3) : "r"(addr));
}
__device__ __forceinline__ void mma16816(float* c,
                                         unsigned a0, unsigned a1,
                                         unsigned a2, unsigned a3,
                                         unsigned b0, unsigned b1) {
    asm volatile("mma.sync.aligned.m16n8k16.row.col.f32.f16.f16.f32 "
                 "{%0,%1,%2,%3}, {%4,%5,%6,%7}, {%8,%9}, {%0,%1,%2,%3};"
                 : "+f"(c[0]), "+f"(c[1]), "+f"(c[2]), "+f"(c[3])
                 : "r"(a0), "r"(a1), "r"(a2), "r"(a3), "r"(b0), "r"(b1));
}

// ==========================================================================
// Kernel 1: fused embedding gather + input GEMM — TENSOR CORE (HMMA fp16).
//   BM=128 BN=128 BK=32; fp16 A/B in smem (pitch 40 halves = conflict-free
//   ldmatrix), fp32 accum. 8 warps in 4x2; each warp computes 32x64 via
//   2x8 m16n8k16 tiles. Double-buffered, one __syncthreads per slice.
// ==========================================================================
#define GP_ 40                          // smem pitch in halves
__global__ void __launch_bounds__(256, 2) k_input_gemm(
    const int*   __restrict__ x,
    const float* __restrict__ emb,
    const float* __restrict__ Wf,  const float* __restrict__ Wb,
    const float* __restrict__ bif, const float* __restrict__ bhf,
    const float* __restrict__ bib, const float* __restrict__ bhb)
{
    __shared__ __align__(16) __half sA[2][128 * GP_];
    __shared__ __align__(16) __half sB[2][128 * GP_];
    __shared__ int sIdx[128];

    const int tid   = threadIdx.x;
    const int lane  = tid & 31;
    const int wid   = tid >> 5;
    const int wm    = wid >> 1;           // 0..3 : 32-row band
    const int wn    = wid & 1;            // 0..1 : 64-col band
    const int m0    = blockIdx.y * 128;
    const int n0g   = blockIdx.x * 128;
    const int dir   = n0g >> 9;
    const int gbase = n0g & 511;
    const float* W  = dir ? Wb : Wf;

    if (tid < 128) sIdx[tid] = x[m0 + tid];
    __syncthreads();

    const int  lrow = tid >> 1;           // 0..127
    const int  lcol = (tid & 1) * 16;     // 0 or 16
    const long aoff = (long)sIdx[lrow] * 300;
    const long boff = (long)(gbase + lrow) * 300;

    float cacc[2][8][4];
#pragma unroll
    for (int mt = 0; mt < 2; mt++)
#pragma unroll
        for (int nt = 0; nt < 8; nt++)
#pragma unroll
            for (int r = 0; r < 4; r++) cacc[mt][nt][r] = 0.0f;

    unsigned stA[8], stB[8];              // staged halves (16 per matrix)

    // ---- load slice k0 into staging regs (LDG + cvt) ----
    auto LD = [&](int k0) {
#pragma unroll
        for (int j = 0; j < 4; j++) {
            int kg = k0 + lcol + 4 * j;
            float4 fa, fb;
            if (kg < 300) {
                fa = *(const float4*)(emb + aoff + kg);
                fb = *(const float4*)(W   + boff + kg);
            } else {
                fa = make_float4(0.f, 0.f, 0.f, 0.f);
                fb = make_float4(0.f, 0.f, 0.f, 0.f);
            }
            __half2 a0 = __floats2half2_rn(fa.x, fa.y);
            __half2 a1 = __floats2half2_rn(fa.z, fa.w);
            __half2 b0 = __floats2half2_rn(fb.x, fb.y);
            __half2 b1 = __floats2half2_rn(fb.z, fb.w);
            stA[2*j]   = *(unsigned*)&a0;  stA[2*j+1] = *(unsigned*)&a1;
            stB[2*j]   = *(unsigned*)&b0;  stB[2*j+1] = *(unsigned*)&b1;
        }
    };
    // ---- store staging regs into smem buffer ----
    auto ST = [&](int buf) {
        uint4 ua0 = make_uint4(stA[0], stA[1], stA[2], stA[3]);
        uint4 ua1 = make_uint4(stA[4], stA[5], stA[6], stA[7]);
        uint4 ub0 = make_uint4(stB[0], stB[1], stB[2], stB[3]);
        uint4 ub1 = make_uint4(stB[4], stB[5], stB[6], stB[7]);
        *(uint4*)&sA[buf][lrow * GP_ + lcol]     = ua0;
        *(uint4*)&sA[buf][lrow * GP_ + lcol + 8] = ua1;
        *(uint4*)&sB[buf][lrow * GP_ + lcol]     = ub0;
        *(uint4*)&sB[buf][lrow * GP_ + lcol + 8] = ub1;
    };

    LD(0); ST(0);
    __syncthreads();

    const unsigned baseA0 = (unsigned)__cvta_generic_to_shared(&sA[0][0]);
    const unsigned baseA1 = (unsigned)__cvta_generic_to_shared(&sA[1][0]);
    const unsigned baseB0 = (unsigned)__cvta_generic_to_shared(&sB[0][0]);
    const unsigned baseB1 = (unsigned)__cvta_generic_to_shared(&sB[1][0]);

    for (int ks = 0; ks < 10; ks++) {
        const int cur = ks & 1;
        if (ks < 9) LD((ks + 1) * 32);    // LDG for next; hides under mma

        const unsigned bA = cur ? baseA1 : baseA0;
        const unsigned bB = cur ? baseB1 : baseB0;
#pragma unroll
        for (int ks2 = 0; ks2 < 2; ks2++) {
            const int k0 = ks2 * 16;
            unsigned a[2][4];
#pragma unroll
            for (int mt = 0; mt < 2; mt++) {
                int row = wm * 32 + mt * 16 + (lane & 15);
                unsigned ad = bA + (unsigned)((row * GP_ + k0 + (lane >> 4) * 8) * 2);
                ldsm4(a[mt][0], a[mt][1], a[mt][2], a[mt][3], ad);
            }
            unsigned b[8][2];
#pragma unroll
            for (int ntp = 0; ntp < 4; ntp++) {
                int nr = wn * 64 + ntp * 16 + (lane & 7) + (lane >> 4) * 8;
                unsigned ad = bB + (unsigned)((nr * GP_ + k0 + ((lane >> 3) & 1) * 8) * 2);
                unsigned r0, r1, r2, r3;
                ldsm4(r0, r1, r2, r3, ad);
                b[2*ntp][0] = r0;  b[2*ntp][1] = r1;
                b[2*ntp+1][0] = r2; b[2*ntp+1][1] = r3;
            }
#pragma unroll
            for (int mt = 0; mt < 2; mt++)
#pragma unroll
                for (int nt = 0; nt < 8; nt++)
                    mma16816(cacc[mt][nt], a[mt][0], a[mt][1], a[mt][2], a[mt][3],
                             b[nt][0], b[nt][1]);
        }
        if (ks < 9) {
            ST(cur ^ 1);
            __syncthreads();
        }
    }

    // epilogue: add bias, write fp32
    const float* bi = dir ? bib : bif;
    const float* bh = dir ? bhb : bhf;
    const int qr = lane >> 2;            // 0..7
    const int qc = (lane & 3) * 2;       // 0,2,4,6
    float* outbase = g_xw + (long)dir * BT_ * G4_;
#pragma unroll
    for (int nt = 0; nt < 8; nt++) {
        int gc = gbase + wn * 64 + nt * 8 + qc;
        float bx = bi[gc] + bh[gc];
        float by = bi[gc + 1] + bh[gc + 1];
#pragma unroll
        for (int mt = 0; mt < 2; mt++) {
            long gm = m0 + wm * 32 + mt * 16 + qr;
            float* o = outbase + gm * G4_ + gc;
            *(float2*)o            = make_float2(cacc[mt][nt][0] + bx,
                                                 cacc[mt][nt][1] + by);
            *(float2*)(o + 8 * G4_) = make_float2(cacc[mt][nt][2] + bx,
                                                  cacc[mt][nt][3] + by);
        }
    }
}

// ==========================================================================
// Kernel 2: LSTM recurrence — HYBRID weight residency (unchanged from R7).
// ==========================================================================
__global__ void __launch_bounds__(256) k_lstm(
    const float* __restrict__ Whf, const float* __restrict__ Whb)
{
    extern __shared__ __align__(16) char smem[];
    uint4* sWs = (uint4*)smem;                      // 16*256*16 = 65536 B
    float* sh  = (float*)(smem + 65536);            // h[128]
    float* sg  = sh + 128;                          // gates[512]

    const int tid = threadIdx.x;
    const int dir = blockIdx.x >> 6;
    const int b   = blockIdx.x & 63;
    const float* Wh = dir ? Whb : Whf;

    for (int idx = tid; idx < 16 * 256; idx += 256) {
        int p4  = idx >> 8;
        int col = idx & 255;
        int g0  = col * 2;
        int k0  = 64 + 4 * p4;
        float4 w0 = *(const float4*)(Wh + (long)(g0    ) * 128 + k0);
        float4 w1 = *(const float4*)(Wh + (long)(g0 + 1) * 128 + k0);
        __half2 t0 = __floats2half2_rn(w0.x, w0.y);
        __half2 t1 = __floats2half2_rn(w1.x, w1.y);
        __half2 t2 = __floats2half2_rn(w0.z, w0.w);
        __half2 t3 = __floats2half2_rn(w1.z, w1.w);
        uint4 u;
        u.x = *(unsigned*)&t0; u.y = *(unsigned*)&t1;
        u.z = *(unsigned*)&t2; u.w = *(unsigned*)&t3;
        sWs[p4 * 256 + col] = u;
    }
    unsigned wA[32], wB[32];
    {
        const float2* r0 = (const float2*)(Wh + (long)(2 * tid)     * 128);
        const float2* r1 = (const float2*)(Wh + (long)(2 * tid + 1) * 128);
#pragma unroll
        for (int p = 0; p < 32; p++) {
            float2 a = r0[p], bb = r1[p];
            __half2 ha = __floats2half2_rn(a.x, a.y);
            __half2 hb = __floats2half2_rn(bb.x, bb.y);
            wA[p] = *(unsigned*)&ha;
            wB[p] = *(unsigned*)&hb;
        }
    }
    if (tid < 128) sh[tid] = 0.0f;
    float c = 0.0f;
    __syncthreads();

    const float* xwp = g_xw + (long)dir * BT_ * G4_ + (long)b * T_ * G4_;
    float* hout = g_h + (long)b * T_ * (2 * H_) + (dir ? H_ : 0);
    const float4* sh4 = (const float4*)sh;

    int t  = dir ? (T_ - 1) : 0;
    const int dt = dir ? -1 : 1;
    const int sec = tid >> 6;

    float2 xv_next = *(const float2*)(xwp + (long)t * G4_ + 2 * tid);

    for (int s = 0; s < T_; s++, t += dt) {
        float2 xv = xv_next;
        if (s + 1 < T_)
            xv_next = *(const float2*)(xwp + (long)(t + dt) * G4_ + 2 * tid);

        float2 accA = make_float2(xv.x, 0.0f);
        float2 accB = make_float2(xv.y, 0.0f);
#pragma unroll
        for (int p4 = 0; p4 < 16; p4++) {
            float4 h4 = sh4[p4];
            float2 h01 = make_float2(h4.x, h4.y);
            float2 h23 = make_float2(h4.z, h4.w);
            accA = ffma2(__half22float2(*(__half2*)&wA[2*p4]),     h01, accA);
            accB = ffma2(__half22float2(*(__half2*)&wB[2*p4]),     h01, accB);
            accA = ffma2(__half22float2(*(__half2*)&wA[2*p4 + 1]), h23, accA);
            accB = ffma2(__half22float2(*(__half2*)&wB[2*p4 + 1]), h23, accB);
        }
#pragma unroll
        for (int p4 = 0; p4 < 16; p4++) {
            float4 h4 = sh4[16 + p4];
            uint4  u  = sWs[p4 * 256 + tid];
            float2 h01 = make_float2(h4.x, h4.y);
            float2 h23 = make_float2(h4.z, h4.w);
            accA = ffma2(__half22float2(*(__half2*)&u.x), h01, accA);
            accB = ffma2(__half22float2(*(__half2*)&u.y), h01, accB);
            accA = ffma2(__half22float2(*(__half2*)&u.z), h23, accA);
            accB = ffma2(__half22float2(*(__half2*)&u.w), h23, accB);
        }
        float gA = accA.x + accA.y;
        float gB = accB.x + accB.y;
        if (sec == 2) { gA = fast_tanh(gA);    gB = fast_tanh(gB); }
        else          { gA = fast_sigmoid(gA); gB = fast_sigmoid(gB); }
        *(float2*)(sg + 2 * tid) = make_float2(gA, gB);
        __syncthreads();
        if (tid < 128) {
            float cc = fmaf(sg[128 + tid], c, sg[tid] * sg[256 + tid]);
            c = cc;
            float hv = sg[384 + tid] * fast_tanh(cc);
            sh[tid] = hv;
            hout[(long)t * (2 * H_) + tid] = hv;
        }
        __syncthreads();
    }
}

// ==========================================================================
// Kernel 3: logits + CRF emission precompute (unchanged).
// ==========================================================================
__global__ void __launch_bounds__(256) k_logits(
    const float* __restrict__ fcW, const float* __restrict__ fcb,
    float* __restrict__ logits)
{
    __shared__ float sW[20 * 257];
    __shared__ float shh[16 * 257];
    __shared__ float sl[16 * 20];
    const int tid = threadIdx.x;
    const long bt0 = (long)blockIdx.x * 16;

    for (int i = tid; i < 20 * 256; i += 256) {
        int cc = i >> 8, k = i & 255;
        sW[cc * 257 + k] = fcW[i];
    }
    for (int i = tid; i < 16 * 256; i += 256) {
        int tk = i >> 8, k = i & 255;
        shh[tk * 257 + k] = g_h[(bt0 + tk) * 256 + k];
    }
    __syncthreads();
    for (int o = tid; o < 16 * 20; o += 256) {
        int tk = o / 20, cc = o % 20;
        const float* hr = shh + tk * 257;
        const float* wr = sW  + cc * 257;
        float a0 = 0.f, a1 = 0.f, a2 = 0.f, a3 = 0.f;
#pragma unroll 16
        for (int k = 0; k < 256; k += 4) {
            a0 = fmaf(hr[k + 0], wr[k + 0], a0);
            a1 = fmaf(hr[k + 1], wr[k + 1], a1);
            a2 = fmaf(hr[k + 2], wr[k + 2], a2);
            a3 = fmaf(hr[k + 3], wr[k + 3], a3);
        }
        float lv = fcb[cc] + ((a0 + a1) + (a2 + a3));
        sl[o] = lv;
        logits[(bt0 + tk) * C_ + cc] = lv;
    }
    __syncthreads();
    for (int o = tid; o < 16 * 20; o += 256) {
        int tk = o / 20, cc = o % 20;
        g_eexp[(bt0 + tk) * C_ + cc] = __expf(sl[o] - sl[tk * 20]);
        if (cc == 0) g_em0[bt0 + tk] = sl[tk * 20];
    }
}

// ==========================================================================
// Kernel 4: CRF — exp-space scan from SMEM-resident tables (unchanged).
// ==========================================================================
__global__ void __launch_bounds__(128) k_crf(
    const float* __restrict__ logits,
    const int*   __restrict__ tags,
    const void*  __restrict__ maskp,
    const float* __restrict__ trans)
{
    __shared__ __align__(16) float sEE[T_ * C_];
    __shared__ __align__(16) float sEM0[T_];
    __shared__ float sT[400];
    __shared__ float sPart[8];
    const int tid  = threadIdx.x;
    const int lane = tid & 31;
    const int wid  = tid >> 5;
    const int b    = blockIdx.x;
    const int isbyte = (((const int*)maskp)[0] == 0x01010101);
    const long mbase = (long)b * T_;

    {
        const float4* src = (const float4*)(g_eexp + mbase * C_);
        float4* dst = (float4*)sEE;
        for (int i = tid; i < (T_ * C_) / 4; i += 128) dst[i] = src[i];
        const float4* s2 = (const float4*)(g_em0 + mbase);
        float4* d2 = (float4*)sEM0;
        for (int i = tid; i < T_ / 4; i += 128) d2[i] = s2[i];
    }
    for (int i = tid; i < 400; i += 128) sT[i] = trans[i];

    int lcnt = 0;
    for (int t = tid; t < T_; t += 128)
        lcnt += (load_mask(maskp, mbase + t, isbyte) != 0);
    for (int o = 16; o; o >>= 1) lcnt += __shfl_xor_sync(0xffffffffu, lcnt, o);
    if (lane == 0) sPart[4 + wid] = (float)lcnt;
    __syncthreads();
    const int len = (int)(sPart[4] + sPart[5] + sPart[6] + sPart[7]);

    const float* lg = logits + mbase * C_;

    if (wid == 0) {
        float Ecol[20];
#pragma unroll
        for (int i = 0; i < 20; i++)
            Ecol[i] = (lane < 20) ? __expf(sT[i * 20 + lane]) : 0.0f;

        float u = (lane < 20) ? sEE[lane] : 0.0f;
        float L = sEM0[0];

        for (int t = 1; t < len; t++) {
            float eeC  = (lane < 20) ? sEE[t * C_ + lane] : 0.0f;
            float em0C = sEM0[t];
            float s0 = 0.f, s1 = 0.f, s2 = 0.f, s3 = 0.f;
#pragma unroll
            for (int i = 0; i < 20; i += 4) {
                s0 = fmaf(__shfl_sync(0xffffffffu, u, i + 0), Ecol[i + 0], s0);
                s1 = fmaf(__shfl_sync(0xffffffffu, u, i + 1), Ecol[i + 1], s1);
                s2 = fmaf(__shfl_sync(0xffffffffu, u, i + 2), Ecol[i + 2], s2);
                s3 = fmaf(__shfl_sync(0xffffffffu, u, i + 3), Ecol[i + 3], s3);
            }
            u = eeC * ((s0 + s1) + (s2 + s3));
            L += em0C;
            if ((t & 3) == 0) {
                float k = __shfl_sync(0xffffffffu, u, 0);
                u *= __fdividef(1.0f, k);
                L += __logf(k);
            }
        }
        float e = u;
        for (int o = 16; o; o >>= 1) e += __shfl_xor_sync(0xffffffffu, e, o);
        if (lane == 0) sPart[0] = L + __logf(e);
    } else {
        const int id = tid - 32;
        float sn = 0.0f;
        for (int t = id; t < len; t += 96)
            sn += lg[t * C_ + tags[mbase + t]];
        for (int t = id; t < len - 1; t += 96)
            sn += sT[tags[mbase + t] * 20 + tags[mbase + t + 1]];
        for (int o = 16; o; o >>= 1) sn += __shfl_xor_sync(0xffffffffu, sn, o);
        if (lane == 0) sPart[wid] = sn;
    }
    __syncthreads();
    if (tid == 0)
        g_res[b] = sPart[0] - (sPart[1] + sPart[2] + sPart[3]);
}

// Kernel 5: deterministic mean over batches -> loss
__global__ void k_final(float* __restrict__ out)
{
    const int lane = threadIdx.x;
    float v = g_res[lane] + g_res[lane + 32];
    for (int o = 16; o; o >>= 1) v += __shfl_xor_sync(0xffffffffu, v, o);
    if (lane == 0) out[0] = v * (1.0f / 64.0f);
}

// ==========================================================================
extern "C" void kernel_launch(void* const* d_in, const int* in_sizes, int n_in,
                              void* d_out, int out_size)
{
    const int*   x      = (const int*)  d_in[0];
    const void*  mask   =               d_in[1];
    const int*   tags   = (const int*)  d_in[2];
    const float* emb    = (const float*)d_in[3];
    const float* W_ih_f = (const float*)d_in[4];
    const float* W_hh_f = (const float*)d_in[5];
    const float* b_ih_f = (const float*)d_in[6];
    const float* b_hh_f = (const float*)d_in[7];
    const float* W_ih_b = (const float*)d_in[8];
    const float* W_hh_b = (const float*)d_in[9];
    const float* b_ih_b = (const float*)d_in[10];
    const float* b_hh_b = (const float*)d_in[11];
    const float* fc_W   = (const float*)d_in[12];
    const float* fc_b   = (const float*)d_in[13];
    const float* trans  = (const float*)d_in[14];

    float* out        = (float*)d_out;
    float* loss_ptr   = out;
    float* logits_ptr = out + 1;
    if (out_size == BT_ * C_) {
        logits_ptr = out;
        loss_ptr   = nullptr;
    }

    const int lstm_smem = 65536 + 128 * 4 + 512 * 4;   // 68096 B
    cudaFuncSetAttribute(k_lstm, cudaFuncAttributeMaxDynamicSharedMemorySize,
                         lstm_smem);

    k_input_gemm<<<dim3(8, 256), 256>>>(x, emb, W_ih_f, W_ih_b,
                                        b_ih_f, b_hh_f, b_ih_b, b_hh_b);
    k_lstm<<<128, 256, lstm_smem>>>(W_hh_f, W_hh_b);
    k_logits<<<BT_ / 16, 256>>>(fc_W, fc_b, logits_ptr);
    k_crf<<<B_, 128>>>(logits_ptr, tags, mask, trans);
    if (loss_ptr) k_final<<<1, 32>>>(loss_ptr);
}

// round 9
// speedup vs baseline: 2.0778x; 1.0888x over previous
#include <cuda_runtime.h>
#include <cuda_fp16.h>
#include <cstdint>

#define B_   64
#define T_   512
#define H_   128
#define E_   300
#define C_   20
#define G4_  512
#define BT_  (B_ * T_)          // 32768
#define V_   100000
#define KP_  320                // K padded for fp16 tables
#define GP_  40                 // GEMM smem pitch in halves

// -------- scratch (static device globals; no runtime allocation) -----------
__device__ __align__(16) __half g_embh[(unsigned)V_ * KP_];    // 64 MB
__device__ __align__(16) __half g_Wh[2u * G4_ * KP_];          // 0.66 MB
__device__ __align__(16) __half g_xwh[2u * BT_ * G4_];         // 64 MB
__device__ __align__(16) float g_h [(unsigned)BT_ * 2 * H_];   // 32 MB
__device__ __align__(16) float g_eexp[(unsigned)BT_ * C_];
__device__ float g_em0[BT_];
__device__ float g_res[B_];

// ----------------------------- math helpers --------------------------------
__device__ __forceinline__ float fast_sigmoid(float x) {
    return __fdividef(1.0f, 1.0f + __expf(-x));
}
__device__ __forceinline__ float fast_tanh(float x) {
    float ax = fabsf(x);
    float e  = __expf(-2.0f * ax);
    float t  = __fdividef(1.0f - e, 1.0f + e);
    return copysignf(t, x);
}
__device__ __forceinline__ int load_mask(const void* m, long idx, int isbyte) {
    return isbyte ? (int)((const unsigned char*)m)[idx] : ((const int*)m)[idx];
}
__device__ __forceinline__ float2 ffma2(float2 a, float2 b, float2 c) {
    unsigned long long ua = *reinterpret_cast<unsigned long long*>(&a);
    unsigned long long ub = *reinterpret_cast<unsigned long long*>(&b);
    unsigned long long uc = *reinterpret_cast<unsigned long long*>(&c);
    unsigned long long ud;
    asm("fma.rn.f32x2 %0, %1, %2, %3;" : "=l"(ud) : "l"(ua), "l"(ub), "l"(uc));
    return *reinterpret_cast<float2*>(&ud);
}
__device__ __forceinline__ void ldsm4(unsigned& r0, unsigned& r1,
                                      unsigned& r2, unsigned& r3,
                                      unsigned addr) {
    asm volatile("ldmatrix.sync.aligned.m8n8.x4.shared.b16 {%0,%1,%2,%3}, [%4];"
                 : "=r"(r0), "=r"(r1), "=r"(r2), "=r"(r3) : "r"(addr));
}
__device__ __forceinline__ void mma16816(float* c,
                                         unsigned a0, unsigned a1,
                                         unsigned a2, unsigned a3,
                                         unsigned b0, unsigned b1) {
    asm volatile("mma.sync.aligned.m16n8k16.row.col.f32.f16.f16.f32 "
                 "{%0,%1,%2,%3}, {%4,%5,%6,%7}, {%8,%9}, {%0,%1,%2,%3};"
                 : "+f"(c[0]), "+f"(c[1]), "+f"(c[2]), "+f"(c[3])
                 : "r"(a0), "r"(a1), "r"(a2), "r"(a3), "r"(b0), "r"(b1));
}
__device__ __forceinline__ void cp16(unsigned dst, const void* src) {
    asm volatile("cp.async.cg.shared.global [%0], [%1], 16;"
                 :: "r"(dst), "l"(src));
}
__device__ __forceinline__ void cp_commit() {
    asm volatile("cp.async.commit_group;");
}
template <int N>
__device__ __forceinline__ void cp_wait() {
    asm volatile("cp.async.wait_group %0;" :: "n"(N));
}

// ==========================================================================
// Kernel 0: one-time fp16 conversion of emb and W_ih (zero-padded to KP_).
// ==========================================================================
__global__ void __launch_bounds__(256) k_cvt(
    const float* __restrict__ emb,
    const float* __restrict__ Wf, const float* __restrict__ Wb)
{
    const long NE = (long)V_ * (KP_ / 2);           // half2 slots for emb
    const long NW = (long)2 * G4_ * (KP_ / 2);
    long i = (long)blockIdx.x * 256 + threadIdx.x;
    if (i < NE) {
        long row = i / (KP_ / 2);
        int  c2  = (int)(i % (KP_ / 2));
        int  col = 2 * c2;
        __half2 v;
        if (col < 300) {
            const float* s = emb + row * 300 + col;
            v = __floats2half2_rn(s[0], s[1]);
        } else v = __floats2half2_rn(0.f, 0.f);
        ((__half2*)g_embh)[i] = v;
    } else if (i < NE + NW) {
        long j   = i - NE;
        long row = j / (KP_ / 2);                   // 0..1023 (dir*512+g)
        int  c2  = (int)(j % (KP_ / 2));
        int  col = 2 * c2;
        const float* W = (row < G4_) ? Wf : Wb;
        long r = (row < G4_) ? row : row - G4_;
        __half2 v;
        if (col < 300) {
            const float* s = W + r * 300 + col;
            v = __floats2half2_rn(s[0], s[1]);
        } else v = __floats2half2_rn(0.f, 0.f);
        ((__half2*)g_Wh)[j] = v;
    }
}

// ==========================================================================
// Kernel 1: fused embedding gather + input GEMM — HMMA + cp.async 3-stage.
//   BM=128 BN=128 BK=32; fp16 tables in gmem, cp.async into smem ring,
//   one __syncthreads per slice, 2-slice prefetch depth. fp16 output.
// ==========================================================================
__global__ void __launch_bounds__(256, 2) k_input_gemm(const int* __restrict__ x)
{
    extern __shared__ __align__(16) char gsm[];
    __half* sA = (__half*)gsm;                       // 3 * 5120 halves
    __half* sB = (__half*)(gsm + 3 * 5120 * 2);
    __shared__ int sIdx[128];

    const int tid   = threadIdx.x;
    const int lane  = tid & 31;
    const int wid   = tid >> 5;
    const int wm    = wid >> 1;
    const int wn    = wid & 1;
    const int m0    = blockIdx.y * 128;
    const int n0g   = blockIdx.x * 128;
    const int dir   = n0g >> 9;
    const int gbase = n0g & 511;

    if (tid < 128) sIdx[tid] = x[m0 + tid];
    __syncthreads();

    const int  lrow = tid >> 1;
    const int  hoff = (tid & 1) * 16;               // halves 0..15 or 16..31
    const __half* srcA = g_embh + (long)sIdx[lrow] * KP_ + hoff;
    const __half* srcB = g_Wh + ((long)dir * G4_ + gbase + lrow) * KP_ + hoff;
    const unsigned sAb = (unsigned)__cvta_generic_to_shared(sA);
    const unsigned sBb = (unsigned)__cvta_generic_to_shared(sB);
    const unsigned dA0 = sAb + (unsigned)((lrow * GP_ + hoff) * 2);
    const unsigned dB0 = sBb + (unsigned)((lrow * GP_ + hoff) * 2);

    float cacc[2][8][4];
#pragma unroll
    for (int mt = 0; mt < 2; mt++)
#pragma unroll
        for (int nt = 0; nt < 8; nt++)
#pragma unroll
            for (int r = 0; r < 4; r++) cacc[mt][nt][r] = 0.0f;

    auto ISSUE = [&](int s) {
        const unsigned bo = (unsigned)((s % 3) * 5120 * 2);
        const __half* a = srcA + s * 32;
        const __half* b = srcB + s * 32;
        cp16(dA0 + bo,      a);
        cp16(dA0 + bo + 16, a + 8);
        cp16(dB0 + bo,      b);
        cp16(dB0 + bo + 16, b + 8);
        cp_commit();
    };

    ISSUE(0); ISSUE(1);

    for (int ks = 0; ks < 10; ks++) {
        cp_wait<1>();            // slice ks landed (ks+1 may be in flight)
        __syncthreads();         // visibility + ring-buffer reuse safety
        if (ks < 8) ISSUE(ks + 2);   // async; overlaps with compute below

        const unsigned bo = (unsigned)((ks % 3) * 5120 * 2);
        const unsigned bA = sAb + bo;
        const unsigned bB = sBb + bo;
#pragma unroll
        for (int ks2 = 0; ks2 < 2; ks2++) {
            const int k0 = ks2 * 16;
            unsigned a[2][4];
#pragma unroll
            for (int mt = 0; mt < 2; mt++) {
                int row = wm * 32 + mt * 16 + (lane & 15);
                unsigned ad = bA + (unsigned)((row * GP_ + k0 + (lane >> 4) * 8) * 2);
                ldsm4(a[mt][0], a[mt][1], a[mt][2], a[mt][3], ad);
            }
            unsigned b[8][2];
#pragma unroll
            for (int ntp = 0; ntp < 4; ntp++) {
                int nr = wn * 64 + ntp * 16 + (lane & 7) + (lane >> 4) * 8;
                unsigned ad = bB + (unsigned)((nr * GP_ + k0 + ((lane >> 3) & 1) * 8) * 2);
                unsigned r0, r1, r2, r3;
                ldsm4(r0, r1, r2, r3, ad);
                b[2*ntp][0] = r0;  b[2*ntp][1] = r1;
                b[2*ntp+1][0] = r2; b[2*ntp+1][1] = r3;
            }
#pragma unroll
            for (int mt = 0; mt < 2; mt++)
#pragma unroll
                for (int nt = 0; nt < 8; nt++)
                    mma16816(cacc[mt][nt], a[mt][0], a[mt][1], a[mt][2], a[mt][3],
                             b[nt][0], b[nt][1]);
        }
    }

    // epilogue: add bias (fetched fp32 from original inputs via g_Wh? biases
    // are separate inputs — passed through constant path below), write fp16.
    // Biases are added here from global fp32 arrays bound via launch params.
    // (see kernel_launch: biases pre-summed into g_bias)
    extern __device__ float g_bias[];                // fwd decl (defined below)
    const int qr = lane >> 2;
    const int qc = (lane & 3) * 2;
    __half* outbase = g_xwh + (long)dir * BT_ * G4_;
    const float* bsum = g_bias + dir * G4_;
#pragma unroll
    for (int nt = 0; nt < 8; nt++) {
        int gc = gbase + wn * 64 + nt * 8 + qc;
        float bx = bsum[gc];
        float by = bsum[gc + 1];
#pragma unroll
        for (int mt = 0; mt < 2; mt++) {
            long gm = m0 + wm * 32 + mt * 16 + qr;
            __half* o = outbase + gm * G4_ + gc;
            *(__half2*)o             = __floats2half2_rn(cacc[mt][nt][0] + bx,
                                                         cacc[mt][nt][1] + by);
            *(__half2*)(o + 8 * G4_) = __floats2half2_rn(cacc[mt][nt][2] + bx,
                                                         cacc[mt][nt][3] + by);
        }
    }
}

__device__ float g_bias[2 * G4_];                    // b_ih + b_hh per dir

__global__ void k_bias(const float* __restrict__ bif, const float* __restrict__ bhf,
                       const float* __restrict__ bib, const float* __restrict__ bhb)
{
    int i = blockIdx.x * 256 + threadIdx.x;
    if (i < G4_)          g_bias[i]        = bif[i] + bhf[i];
    else if (i < 2 * G4_) g_bias[i]        = bib[i - G4_] + bhb[i - G4_];
}

// ==========================================================================
// Kernel 2: LSTM recurrence — HYBRID weight residency; xw now fp16.
// ==========================================================================
__global__ void __launch_bounds__(256) k_lstm(
    const float* __restrict__ Whf, const float* __restrict__ Whb)
{
    extern __shared__ __align__(16) char smem[];
    uint4* sWs = (uint4*)smem;                      // 16*256*16 = 65536 B
    float* sh  = (float*)(smem + 65536);            // h[128]
    float* sg  = sh + 128;                          // gates[512]

    const int tid = threadIdx.x;
    const int dir = blockIdx.x >> 6;
    const int b   = blockIdx.x & 63;
    const float* Wh = dir ? Whb : Whf;

    for (int idx = tid; idx < 16 * 256; idx += 256) {
        int p4  = idx >> 8;
        int col = idx & 255;
        int g0  = col * 2;
        int k0  = 64 + 4 * p4;
        float4 w0 = *(const float4*)(Wh + (long)(g0    ) * 128 + k0);
        float4 w1 = *(const float4*)(Wh + (long)(g0 + 1) * 128 + k0);
        __half2 t0 = __floats2half2_rn(w0.x, w0.y);
        __half2 t1 = __floats2half2_rn(w1.x, w1.y);
        __half2 t2 = __floats2half2_rn(w0.z, w0.w);
        __half2 t3 = __floats2half2_rn(w1.z, w1.w);
        uint4 u;
        u.x = *(unsigned*)&t0; u.y = *(unsigned*)&t1;
        u.z = *(unsigned*)&t2; u.w = *(unsigned*)&t3;
        sWs[p4 * 256 + col] = u;
    }
    unsigned wA[32], wB[32];
    {
        const float2* r0 = (const float2*)(Wh + (long)(2 * tid)     * 128);
        const float2* r1 = (const float2*)(Wh + (long)(2 * tid + 1) * 128);
#pragma unroll
        for (int p = 0; p < 32; p++) {
            float2 a = r0[p], bb = r1[p];
            __half2 ha = __floats2half2_rn(a.x, a.y);
            __half2 hb = __floats2half2_rn(bb.x, bb.y);
            wA[p] = *(unsigned*)&ha;
            wB[p] = *(unsigned*)&hb;
        }
    }
    if (tid < 128) sh[tid] = 0.0f;
    float c = 0.0f;
    __syncthreads();

    const __half2* xwp = (const __half2*)(g_xwh + (long)dir * BT_ * G4_
                                          + (long)b * T_ * G4_);
    float* hout = g_h + (long)b * T_ * (2 * H_) + (dir ? H_ : 0);
    const float4* sh4 = (const float4*)sh;

    int t  = dir ? (T_ - 1) : 0;
    const int dt = dir ? -1 : 1;
    const int sec = tid >> 6;

    __half2 xv_next = xwp[(long)t * 256 + tid];

    for (int s = 0; s < T_; s++, t += dt) {
        float2 xv = __half22float2(xv_next);
        if (s + 1 < T_)
            xv_next = xwp[(long)(t + dt) * 256 + tid];

        float2 accA = make_float2(xv.x, 0.0f);
        float2 accB = make_float2(xv.y, 0.0f);
#pragma unroll
        for (int p4 = 0; p4 < 16; p4++) {
            float4 h4 = sh4[p4];
            float2 h01 = make_float2(h4.x, h4.y);
            float2 h23 = make_float2(h4.z, h4.w);
            accA = ffma2(__half22float2(*(__half2*)&wA[2*p4]),     h01, accA);
            accB = ffma2(__half22float2(*(__half2*)&wB[2*p4]),     h01, accB);
            accA = ffma2(__half22float2(*(__half2*)&wA[2*p4 + 1]), h23, accA);
            accB = ffma2(__half22float2(*(__half2*)&wB[2*p4 + 1]), h23, accB);
        }
#pragma unroll
        for (int p4 = 0; p4 < 16; p4++) {
            float4 h4 = sh4[16 + p4];
            uint4  u  = sWs[p4 * 256 + tid];
            float2 h01 = make_float2(h4.x, h4.y);
            float2 h23 = make_float2(h4.z, h4.w);
            accA = ffma2(__half22float2(*(__half2*)&u.x), h01, accA);
            accB = ffma2(__half22float2(*(__half2*)&u.y), h01, accB);
            accA = ffma2(__half22float2(*(__half2*)&u.z), h23, accA);
            accB = ffma2(__half22float2(*(__half2*)&u.w), h23, accB);
        }
        float gA = accA.x + accA.y;
        float gB = accB.x + accB.y;
        if (sec == 2) { gA = fast_tanh(gA);    gB = fast_tanh(gB); }
        else          { gA = fast_sigmoid(gA); gB = fast_sigmoid(gB); }
        *(float2*)(sg + 2 * tid) = make_float2(gA, gB);
        __syncthreads();
        if (tid < 128) {
            float cc = fmaf(sg[128 + tid], c, sg[tid] * sg[256 + tid]);
            c = cc;
            float hv = sg[384 + tid] * fast_tanh(cc);
            sh[tid] = hv;
            hout[(long)t * (2 * H_) + tid] = hv;
        }
        __syncthreads();
    }
}

// ==========================================================================
// Kernel 3: logits + CRF emission precompute (unchanged).
// ==========================================================================
__global__ void __launch_bounds__(256) k_logits(
    const float* __restrict__ fcW, const float* __restrict__ fcb,
    float* __restrict__ logits)
{
    __shared__ float sW[20 * 257];
    __shared__ float shh[16 * 257];
    __shared__ float sl[16 * 20];
    const int tid = threadIdx.x;
    const long bt0 = (long)blockIdx.x * 16;

    for (int i = tid; i < 20 * 256; i += 256) {
        int cc = i >> 8, k = i & 255;
        sW[cc * 257 + k] = fcW[i];
    }
    for (int i = tid; i < 16 * 256; i += 256) {
        int tk = i >> 8, k = i & 255;
        shh[tk * 257 + k] = g_h[(bt0 + tk) * 256 + k];
    }
    __syncthreads();
    for (int o = tid; o < 16 * 20; o += 256) {
        int tk = o / 20, cc = o % 20;
        const float* hr = shh + tk * 257;
        const float* wr = sW  + cc * 257;
        float a0 = 0.f, a1 = 0.f, a2 = 0.f, a3 = 0.f;
#pragma unroll 16
        for (int k = 0; k < 256; k += 4) {
            a0 = fmaf(hr[k + 0], wr[k + 0], a0);
            a1 = fmaf(hr[k + 1], wr[k + 1], a1);
            a2 = fmaf(hr[k + 2], wr[k + 2], a2);
            a3 = fmaf(hr[k + 3], wr[k + 3], a3);
        }
        float lv = fcb[cc] + ((a0 + a1) + (a2 + a3));
        sl[o] = lv;
        logits[(bt0 + tk) * C_ + cc] = lv;
    }
    __syncthreads();
    for (int o = tid; o < 16 * 20; o += 256) {
        int tk = o / 20, cc = o % 20;
        g_eexp[(bt0 + tk) * C_ + cc] = __expf(sl[o] - sl[tk * 20]);
        if (cc == 0) g_em0[bt0 + tk] = sl[tk * 20];
    }
}

// ==========================================================================
// Kernel 4: CRF — exp-space scan from SMEM-resident tables (unchanged).
// ==========================================================================
__global__ void __launch_bounds__(128) k_crf(
    const float* __restrict__ logits,
    const int*   __restrict__ tags,
    const void*  __restrict__ maskp,
    const float* __restrict__ trans)
{
    __shared__ __align__(16) float sEE[T_ * C_];
    __shared__ __align__(16) float sEM0[T_];
    __shared__ float sT[400];
    __shared__ float sPart[8];
    const int tid  = threadIdx.x;
    const int lane = tid & 31;
    const int wid  = tid >> 5;
    const int b    = blockIdx.x;
    const int isbyte = (((const int*)maskp)[0] == 0x01010101);
    const long mbase = (long)b * T_;

    {
        const float4* src = (const float4*)(g_eexp + mbase * C_);
        float4* dst = (float4*)sEE;
        for (int i = tid; i < (T_ * C_) / 4; i += 128) dst[i] = src[i];
        const float4* s2 = (const float4*)(g_em0 + mbase);
        float4* d2 = (float4*)sEM0;
        for (int i = tid; i < T_ / 4; i += 128) d2[i] = s2[i];
    }
    for (int i = tid; i < 400; i += 128) sT[i] = trans[i];

    int lcnt = 0;
    for (int t = tid; t < T_; t += 128)
        lcnt += (load_mask(maskp, mbase + t, isbyte) != 0);
    for (int o = 16; o; o >>= 1) lcnt += __shfl_xor_sync(0xffffffffu, lcnt, o);
    if (lane == 0) sPart[4 + wid] = (float)lcnt;
    __syncthreads();
    const int len = (int)(sPart[4] + sPart[5] + sPart[6] + sPart[7]);

    const float* lg = logits + mbase * C_;

    if (wid == 0) {
        float Ecol[20];
#pragma unroll
        for (int i = 0; i < 20; i++)
            Ecol[i] = (lane < 20) ? __expf(sT[i * 20 + lane]) : 0.0f;

        float u = (lane < 20) ? sEE[lane] : 0.0f;
        float L = sEM0[0];

        for (int t = 1; t < len; t++) {
            float eeC  = (lane < 20) ? sEE[t * C_ + lane] : 0.0f;
            float em0C = sEM0[t];
            float s0 = 0.f, s1 = 0.f, s2 = 0.f, s3 = 0.f;
#pragma unroll
            for (int i = 0; i < 20; i += 4) {
                s0 = fmaf(__shfl_sync(0xffffffffu, u, i + 0), Ecol[i + 0], s0);
                s1 = fmaf(__shfl_sync(0xffffffffu, u, i + 1), Ecol[i + 1], s1);
                s2 = fmaf(__shfl_sync(0xffffffffu, u, i + 2), Ecol[i + 2], s2);
                s3 = fmaf(__shfl_sync(0xffffffffu, u, i + 3), Ecol[i + 3], s3);
            }
            u = eeC * ((s0 + s1) + (s2 + s3));
            L += em0C;
            if ((t & 3) == 0) {
                float k = __shfl_sync(0xffffffffu, u, 0);
                u *= __fdividef(1.0f, k);
                L += __logf(k);
            }
        }
        float e = u;
        for (int o = 16; o; o >>= 1) e += __shfl_xor_sync(0xffffffffu, e, o);
        if (lane == 0) sPart[0] = L + __logf(e);
    } else {
        const int id = tid - 32;
        float sn = 0.0f;
        for (int t = id; t < len; t += 96)
            sn += lg[t * C_ + tags[mbase + t]];
        for (int t = id; t < len - 1; t += 96)
            sn += sT[tags[mbase + t] * 20 + tags[mbase + t + 1]];
        for (int o = 16; o; o >>= 1) sn += __shfl_xor_sync(0xffffffffu, sn, o);
        if (lane == 0) sPart[wid] = sn;
    }
    __syncthreads();
    if (tid == 0)
        g_res[b] = sPart[0] - (sPart[1] + sPart[2] + sPart[3]);
}

// Kernel 5: deterministic mean over batches -> loss
__global__ void k_final(float* __restrict__ out)
{
    const int lane = threadIdx.x;
    float v = g_res[lane] + g_res[lane + 32];
    for (int o = 16; o; o >>= 1) v += __shfl_xor_sync(0xffffffffu, v, o);
    if (lane == 0) out[0] = v * (1.0f / 64.0f);
}

// ==========================================================================
extern "C" void kernel_launch(void* const* d_in, const int* in_sizes, int n_in,
                              void* d_out, int out_size)
{
    const int*   x      = (const int*)  d_in[0];
    const void*  mask   =               d_in[1];
    const int*   tags   = (const int*)  d_in[2];
    const float* emb    = (const float*)d_in[3];
    const float* W_ih_f = (const float*)d_in[4];
    const float* W_hh_f = (const float*)d_in[5];
    const float* b_ih_f = (const float*)d_in[6];
    const float* b_hh_f = (const float*)d_in[7];
    const float* W_ih_b = (const float*)d_in[8];
    const float* W_hh_b = (const float*)d_in[9];
    const float* b_ih_b = (const float*)d_in[10];
    const float* b_hh_b = (const float*)d_in[11];
    const float* fc_W   = (const float*)d_in[12];
    const float* fc_b   = (const float*)d_in[13];
    const float* trans  = (const float*)d_in[14];

    float* out        = (float*)d_out;
    float* loss_ptr   = out;
    float* logits_ptr = out + 1;
    if (out_size == BT_ * C_) {
        logits_ptr = out;
        loss_ptr   = nullptr;
    }

    const int gemm_smem = 2 * 3 * 5120 * 2;             // 61440 B
    cudaFuncSetAttribute(k_input_gemm,
                         cudaFuncAttributeMaxDynamicSharedMemorySize, gemm_smem);
    const int lstm_smem = 65536 + 128 * 4 + 512 * 4;    // 68096 B
    cudaFuncSetAttribute(k_lstm, cudaFuncAttributeMaxDynamicSharedMemorySize,
                         lstm_smem);

    {   // fp16 tables + bias precompute
        long ntot = (long)V_ * (KP_ / 2) + (long)2 * G4_ * (KP_ / 2);
        int nblk = (int)((ntot + 255) / 256);
        k_cvt<<<nblk, 256>>>(emb, W_ih_f, W_ih_b);
        k_bias<<<(2 * G4_ + 255) / 256, 256>>>(b_ih_f, b_hh_f, b_ih_b, b_hh_b);
    }
    k_input_gemm<<<dim3(8, 256), 256, gemm_smem>>>(x);
    k_lstm<<<128, 256, lstm_smem>>>(W_hh_f, W_hh_b);
    k_logits<<<BT_ / 16, 256>>>(fc_W, fc_b, logits_ptr);
    k_crf<<<B_, 128>>>(logits_ptr, tags, mask, trans);
    if (loss_ptr) k_final<<<1, 32>>>(loss_ptr);
}